// round 2
// baseline (speedup 1.0000x reference)
#include <cuda_runtime.h>
#include <cuda_bf16.h>
#include <math.h>

// Problem constants (from reference): B=2, L=2048, H=16, Dh=64, D=1024
#define BB 2
#define LL 2048
#define NH 16
#define DH 64
#define DM 1024
#define MROWS (BB * LL)          // 4096
#define PAD_START 1792           // keys >= this are masked (static in reference)
#define ATTN_SCALE 0.125f        // 1/sqrt(64)

// Scratch (allocation-free rule: __device__ globals)
__device__ float g_Q[MROWS * DM];
__device__ float g_K[MROWS * DM];
__device__ float g_V[MROWS * DM];
__device__ float g_C[MROWS * DM];

// ---------------------------------------------------------------------------
// GEMM: Y[M,N] = X[M,K] @ W[N,K]^T + b[N]   (torch Linear convention)
// 64x64 tile, BK=16, 256 threads, 4x4 microtile per thread.
// ---------------------------------------------------------------------------
#define TM 64
#define TN 64
#define TK 16

__global__ __launch_bounds__(256) void gemm_bias_kernel(
    const float* __restrict__ X, const float* __restrict__ W,
    const float* __restrict__ bias, float* __restrict__ Y,
    int M, int N, int K)
{
    __shared__ float Xs[TM][TK + 1];
    __shared__ float Ws[TN][TK + 1];

    const int tx = threadIdx.x;   // 0..15
    const int ty = threadIdx.y;   // 0..15
    const int tid = ty * 16 + tx;
    const int row0 = blockIdx.y * TM;
    const int col0 = blockIdx.x * TN;

    float acc[4][4];
#pragma unroll
    for (int i = 0; i < 4; i++)
#pragma unroll
        for (int j = 0; j < 4; j++) acc[i][j] = 0.f;

    for (int k0 = 0; k0 < K; k0 += TK) {
#pragma unroll
        for (int i = 0; i < 4; i++) {
            int idx = tid + i * 256;          // 0..1023
            int r = idx / TK, c = idx % TK;
            Xs[r][c] = X[(size_t)(row0 + r) * K + k0 + c];
            Ws[r][c] = W[(size_t)(col0 + r) * K + k0 + c];
        }
        __syncthreads();
#pragma unroll
        for (int kk = 0; kk < TK; kk++) {
            float xv[4], wv[4];
#pragma unroll
            for (int i = 0; i < 4; i++) xv[i] = Xs[ty * 4 + i][kk];
#pragma unroll
            for (int j = 0; j < 4; j++) wv[j] = Ws[tx * 4 + j][kk];
#pragma unroll
            for (int i = 0; i < 4; i++)
#pragma unroll
                for (int j = 0; j < 4; j++) acc[i][j] += xv[i] * wv[j];
        }
        __syncthreads();
    }

#pragma unroll
    for (int i = 0; i < 4; i++) {
        int r = row0 + ty * 4 + i;
#pragma unroll
        for (int j = 0; j < 4; j++) {
            int c = col0 + tx * 4 + j;
            Y[(size_t)r * N + c] = acc[i][j] + bias[c];
        }
    }
}

// ---------------------------------------------------------------------------
// Flash-attention (fp32, online softmax).
// grid = (L/BR, NH, BB), block = BR = 128 threads; one q-row per thread.
// K/V tiles (64x64) staged in smem, read as broadcast float4.
// Scores staged in padded smem (stride 65) to keep registers at q[64]+acc[64].
// ---------------------------------------------------------------------------
#define BR 128
#define BC 64
// dynamic smem floats: Ks 64*64, Vs 64*64, Ss BR*65
#define ATTN_SMEM_FLOATS (2 * BC * DH + BR * 65)
#define ATTN_SMEM_BYTES (ATTN_SMEM_FLOATS * 4)

__global__ __launch_bounds__(BR) void attn_kernel(
    const float* __restrict__ Q, const float* __restrict__ K,
    const float* __restrict__ V, float* __restrict__ O)
{
    extern __shared__ float smem[];
    float* Ks = smem;                    // [BC][DH]
    float* Vs = smem + BC * DH;          // [BC][DH]
    float* Ss = smem + 2 * BC * DH;      // [BR][65]

    const int t = threadIdx.x;
    const int h = blockIdx.y;
    const int b = blockIdx.z;
    const int q0 = blockIdx.x * BR;
    const int l = q0 + t;                // query index within batch

    const float* qptr = Q + (size_t)(b * LL + l) * DM + h * DH;
    float q[DH];
#pragma unroll
    for (int c4 = 0; c4 < DH / 4; c4++) {
        float4 v = *(const float4*)(qptr + c4 * 4);
        q[c4 * 4 + 0] = v.x; q[c4 * 4 + 1] = v.y;
        q[c4 * 4 + 2] = v.z; q[c4 * 4 + 3] = v.w;
    }

    float acc[DH];
#pragma unroll
    for (int c = 0; c < DH; c++) acc[c] = 0.f;
    float m = -1e30f, lsum = 0.f;

    const int kv_limit_thread = min(l + 1, PAD_START);
    const int kv_limit_block  = min(q0 + BR, PAD_START);

    for (int k0 = 0; k0 < kv_limit_block; k0 += BC) {
        // stage K/V tile: BC*DH floats = 1024 float4, 128 threads -> 8 iters
        const int rowbase = b * LL + k0;
        for (int i = t; i < BC * DH / 4; i += BR) {
            int r = i >> 4;            // 16 float4 per row
            int c4 = i & 15;
            ((float4*)Ks)[i] = *(const float4*)(K + (size_t)(rowbase + r) * DM + h * DH + c4 * 4);
            ((float4*)Vs)[i] = *(const float4*)(V + (size_t)(rowbase + r) * DM + h * DH + c4 * 4);
        }
        __syncthreads();

        const int jmax = kv_limit_thread - k0;  // may be <=0 (fully masked tile)
        float tmax = -1e30f;
#pragma unroll 4
        for (int j = 0; j < BC; j++) {
            float s = 0.f;
            const float4* kr = (const float4*)(Ks + j * DH);
#pragma unroll
            for (int c4 = 0; c4 < DH / 4; c4++) {
                float4 kv = kr[c4];
                s += q[c4 * 4 + 0] * kv.x;
                s += q[c4 * 4 + 1] * kv.y;
                s += q[c4 * 4 + 2] * kv.z;
                s += q[c4 * 4 + 3] * kv.w;
            }
            s = (j < jmax) ? s * ATTN_SCALE : -1e30f;
            tmax = fmaxf(tmax, s);
            Ss[t * 65 + j] = s;
        }

        float mnew = fmaxf(m, tmax);
        float corr = __expf(m - mnew);
        lsum *= corr;
#pragma unroll
        for (int c = 0; c < DH; c++) acc[c] *= corr;
        m = mnew;

#pragma unroll 2
        for (int j = 0; j < BC; j++) {
            float p = __expf(Ss[t * 65 + j] - mnew);
            lsum += p;
            const float4* vr = (const float4*)(Vs + j * DH);
#pragma unroll
            for (int c4 = 0; c4 < DH / 4; c4++) {
                float4 vv = vr[c4];
                acc[c4 * 4 + 0] += p * vv.x;
                acc[c4 * 4 + 1] += p * vv.y;
                acc[c4 * 4 + 2] += p * vv.z;
                acc[c4 * 4 + 3] += p * vv.w;
            }
        }
        __syncthreads();
    }

    const float inv = 1.f / lsum;
    float* optr = O + (size_t)(b * LL + l) * DM + h * DH;
#pragma unroll
    for (int c4 = 0; c4 < DH / 4; c4++) {
        float4 o4;
        o4.x = acc[c4 * 4 + 0] * inv;
        o4.y = acc[c4 * 4 + 1] * inv;
        o4.z = acc[c4 * 4 + 2] * inv;
        o4.w = acc[c4 * 4 + 3] * inv;
        *(float4*)(optr + c4 * 4) = o4;
    }
}

// ---------------------------------------------------------------------------
extern "C" void kernel_launch(void* const* d_in, const int* in_sizes, int n_in,
                              void* d_out, int out_size)
{
    const float* X  = (const float*)d_in[0];
    const float* Wq = (const float*)d_in[1];
    const float* bq = (const float*)d_in[2];
    const float* Wk = (const float*)d_in[3];
    const float* bk = (const float*)d_in[4];
    const float* Wv = (const float*)d_in[5];
    const float* bv = (const float*)d_in[6];
    const float* Wo = (const float*)d_in[7];
    const float* bo = (const float*)d_in[8];
    float* out = (float*)d_out;

    float *Qp, *Kp, *Vp, *Cp;
    cudaGetSymbolAddress((void**)&Qp, g_Q);
    cudaGetSymbolAddress((void**)&Kp, g_K);
    cudaGetSymbolAddress((void**)&Vp, g_V);
    cudaGetSymbolAddress((void**)&Cp, g_C);

    cudaFuncSetAttribute(attn_kernel,
                         cudaFuncAttributeMaxDynamicSharedMemorySize,
                         ATTN_SMEM_BYTES);

    dim3 ggrid(DM / TN, MROWS / TM);   // (16, 64)
    dim3 gblk(16, 16);

    gemm_bias_kernel<<<ggrid, gblk>>>(X, Wq, bq, Qp, MROWS, DM, DM);
    gemm_bias_kernel<<<ggrid, gblk>>>(X, Wk, bk, Kp, MROWS, DM, DM);
    gemm_bias_kernel<<<ggrid, gblk>>>(X, Wv, bv, Vp, MROWS, DM, DM);

    dim3 agrid(LL / BR, NH, BB);       // (16, 16, 2)
    attn_kernel<<<agrid, BR, ATTN_SMEM_BYTES>>>(Qp, Kp, Vp, Cp);

    gemm_bias_kernel<<<ggrid, gblk>>>(Cp, Wo, bo, out, MROWS, DM, DM);
}

// round 4
// speedup vs baseline: 4.7297x; 4.7297x over previous
#include <cuda_runtime.h>
#include <cuda_bf16.h>
#include <stdint.h>

// B=2, L=2048, H=16, Dh=64, D=1024
#define BB 2
#define LL 2048
#define NH 16
#define DH 64
#define DM 1024
#define MROWS (BB * LL)
#define PAD_TILES 28                   // keys >= 1792 masked; 1792/64
#define SCALE2 0.18033688011112042f    // (1/8) * log2(e)

__device__ float         g_Q[(size_t)MROWS * DM];
__device__ float         g_K[(size_t)MROWS * DM];
__device__ __nv_bfloat16 g_Vhi[(size_t)MROWS * DM];
__device__ __nv_bfloat16 g_Vlo[(size_t)MROWS * DM];
__device__ float         g_C[(size_t)MROWS * DM];

// ---------------- PTX helpers ----------------
__device__ __forceinline__ uint32_t smem_u32(const void* p) {
    return (uint32_t)__cvta_generic_to_shared(p);
}
__device__ __forceinline__ void cp16(uint32_t s, const void* g) {
    asm volatile("cp.async.cg.shared.global [%0], [%1], 16;" :: "r"(s), "l"(g));
}
__device__ __forceinline__ void cp_commit() {
    asm volatile("cp.async.commit_group;" ::: "memory");
}
template <int N> __device__ __forceinline__ void cp_wait() {
    asm volatile("cp.async.wait_group %0;" :: "n"(N) : "memory");
}
__device__ __forceinline__ uint32_t f2tf(float x) {
    uint32_t u; asm("cvt.rna.tf32.f32 %0, %1;" : "=r"(u) : "f"(x)); return u;
}
__device__ __forceinline__ float ex2(float x) {
    float r; asm("ex2.approx.f32 %0, %1;" : "=f"(r) : "f"(x)); return r;
}
__device__ __forceinline__ void mma_tf32(float* d, const uint32_t* a, const uint32_t* b) {
    asm volatile("mma.sync.aligned.m16n8k8.row.col.f32.tf32.tf32.f32 "
        "{%0,%1,%2,%3},{%4,%5,%6,%7},{%8,%9},{%0,%1,%2,%3};"
        : "+f"(d[0]), "+f"(d[1]), "+f"(d[2]), "+f"(d[3])
        : "r"(a[0]), "r"(a[1]), "r"(a[2]), "r"(a[3]), "r"(b[0]), "r"(b[1]));
}
__device__ __forceinline__ void mma_bf16(float* d, const uint32_t* a, const uint32_t* b) {
    asm volatile("mma.sync.aligned.m16n8k16.row.col.f32.bf16.bf16.f32 "
        "{%0,%1,%2,%3},{%4,%5,%6,%7},{%8,%9},{%0,%1,%2,%3};"
        : "+f"(d[0]), "+f"(d[1]), "+f"(d[2]), "+f"(d[3])
        : "r"(a[0]), "r"(a[1]), "r"(a[2]), "r"(a[3]), "r"(b[0]), "r"(b[1]));
}
__device__ __forceinline__ void ldsm4t(uint32_t* r, uint32_t a) {
    asm volatile("ldmatrix.sync.aligned.m8n8.x4.trans.shared.b16 {%0,%1,%2,%3},[%4];"
                 : "=r"(r[0]), "=r"(r[1]), "=r"(r[2]), "=r"(r[3]) : "r"(a));
}
// Split a pair of floats into bf16 hi + bf16 residual (Dekker split).
__device__ __forceinline__ uint32_t pack_split(float a, float b, uint32_t& lo) {
    __nv_bfloat162 h = __floats2bfloat162_rn(a, b);
    float2 hf = __bfloat1622float2(h);
    __nv_bfloat162 l = __floats2bfloat162_rn(a - hf.x, b - hf.y);
    lo = *(uint32_t*)&l;
    return *(uint32_t*)&h;
}

// ---------------------------------------------------------------------------
// tf32 GEMM core: 128x128 tile, BK=32, 256 thr (8 warps 2x4), warp 64x32,
// cp.async double buffer. acc[4][4][4] computed; epilogue differs per kernel.
// ---------------------------------------------------------------------------
#define GBK 32
#define GLD 36
#define GEMM_SMEM_BYTES (2 * 2 * 128 * GLD * 4)

#define GEMM_MAIN(APTR, WPTR)                                                   \
    float* As = dsm;                                                            \
    float* Bs = dsm + 2 * 128 * GLD;                                            \
    const int lane = tid & 31, wid = tid >> 5;                                  \
    const int wm = wid >> 2, wn = wid & 3;                                      \
    float acc[4][4][4];                                                         \
    _Pragma("unroll") for (int i = 0; i < 4; i++)                               \
    _Pragma("unroll") for (int j = 0; j < 4; j++)                               \
    _Pragma("unroll") for (int r = 0; r < 4; r++) acc[i][j][r] = 0.f;           \
    auto load_tiles = [&](int kt, int st) {                                     \
        const int k0 = kt * GBK;                                                \
        float* as = As + st * 128 * GLD;                                        \
        float* bs = Bs + st * 128 * GLD;                                        \
        _Pragma("unroll") for (int j = 0; j < 4; j++) {                         \
            int ci = tid + j * 256;                                             \
            int r = ci >> 3, c = ci & 7;                                        \
            cp16(smem_u32(as + r * GLD + c * 4), (APTR) + (size_t)(row0 + r) * DM + k0 + c * 4); \
            cp16(smem_u32(bs + r * GLD + c * 4), (WPTR) + (size_t)(col0 + r) * DM + k0 + c * 4); \
        }                                                                       \
    };                                                                          \
    load_tiles(0, 0);                                                           \
    cp_commit();                                                                \
    const int NTk = DM / GBK;                                                   \
    for (int kt = 0; kt < NTk; ++kt) {                                          \
        const int st = kt & 1;                                                  \
        if (kt + 1 < NTk) { load_tiles(kt + 1, st ^ 1); cp_commit(); cp_wait<1>(); } \
        else              { cp_wait<0>(); }                                     \
        __syncthreads();                                                        \
        const float* as = As + st * 128 * GLD;                                  \
        const float* bs = Bs + st * 128 * GLD;                                  \
        _Pragma("unroll") for (int ks = 0; ks < 4; ++ks) {                      \
            const int kk = ks * 8;                                              \
            uint32_t af[4][4], bf[4][2];                                        \
            _Pragma("unroll") for (int mt = 0; mt < 4; ++mt) {                  \
                const float* p = as + (size_t)(wm * 64 + mt * 16 + (lane >> 2)) * GLD + kk + (lane & 3); \
                af[mt][0] = f2tf(p[0]);  af[mt][1] = f2tf(p[8 * GLD]);          \
                af[mt][2] = f2tf(p[4]);  af[mt][3] = f2tf(p[8 * GLD + 4]);      \
            }                                                                   \
            _Pragma("unroll") for (int nt = 0; nt < 4; ++nt) {                  \
                const float* p = bs + (size_t)(wn * 32 + nt * 8 + (lane >> 2)) * GLD + kk + (lane & 3); \
                bf[nt][0] = f2tf(p[0]);  bf[nt][1] = f2tf(p[4]);                \
            }                                                                   \
            _Pragma("unroll") for (int mt = 0; mt < 4; ++mt)                    \
            _Pragma("unroll") for (int nt = 0; nt < 4; ++nt)                    \
                mma_tf32(acc[mt][nt], af[mt], bf[nt]);                          \
        }                                                                       \
        __syncthreads();                                                        \
    }

// QKV fused projection: blockIdx.z selects {Q, K, V}. V writes split bf16.
__global__ __launch_bounds__(256) void qkv_gemm(
    const float* __restrict__ X,
    const float* __restrict__ Wq, const float* __restrict__ bq,
    const float* __restrict__ Wk, const float* __restrict__ bk,
    const float* __restrict__ Wv, const float* __restrict__ bv,
    float* __restrict__ Qo, float* __restrict__ Ko,
    __nv_bfloat16* __restrict__ Vhi, __nv_bfloat16* __restrict__ Vlo)
{
    extern __shared__ float dsm[];
    const int tid = threadIdx.x;
    const int row0 = blockIdx.y * 128, col0 = blockIdx.x * 128;
    const int z = blockIdx.z;
    const float* W    = (z == 0) ? Wq : (z == 1) ? Wk : Wv;
    const float* bias = (z == 0) ? bq : (z == 1) ? bk : bv;

    GEMM_MAIN(X, W)

#pragma unroll
    for (int mt = 0; mt < 4; ++mt) {
        const int r = row0 + wm * 64 + mt * 16 + (lane >> 2);
#pragma unroll
        for (int nt = 0; nt < 4; ++nt) {
            const int c = col0 + wn * 32 + nt * 8 + (lane & 3) * 2;
            const float b0 = bias[c], b1 = bias[c + 1];
            const float v0 = acc[mt][nt][0] + b0, v1 = acc[mt][nt][1] + b1;
            const float v2 = acc[mt][nt][2] + b0, v3 = acc[mt][nt][3] + b1;
            if (z == 2) {
                uint32_t lo0, lo1;
                uint32_t hi0 = pack_split(v0, v1, lo0);
                uint32_t hi1 = pack_split(v2, v3, lo1);
                *(uint32_t*)(Vhi + (size_t)r * DM + c)       = hi0;
                *(uint32_t*)(Vlo + (size_t)r * DM + c)       = lo0;
                *(uint32_t*)(Vhi + (size_t)(r + 8) * DM + c) = hi1;
                *(uint32_t*)(Vlo + (size_t)(r + 8) * DM + c) = lo1;
            } else {
                float* out = (z == 0) ? Qo : Ko;
                *(float2*)(out + (size_t)r * DM + c)       = make_float2(v0, v1);
                *(float2*)(out + (size_t)(r + 8) * DM + c) = make_float2(v2, v3);
            }
        }
    }
}

// Output projection: fp32 out.
__global__ __launch_bounds__(256) void out_gemm(
    const float* __restrict__ A, const float* __restrict__ W,
    const float* __restrict__ bias, float* __restrict__ Y)
{
    extern __shared__ float dsm[];
    const int tid = threadIdx.x;
    const int row0 = blockIdx.y * 128, col0 = blockIdx.x * 128;

    GEMM_MAIN(A, W)

#pragma unroll
    for (int mt = 0; mt < 4; ++mt) {
        const int r = row0 + wm * 64 + mt * 16 + (lane >> 2);
#pragma unroll
        for (int nt = 0; nt < 4; ++nt) {
            const int c = col0 + wn * 32 + nt * 8 + (lane & 3) * 2;
            const float b0 = bias[c], b1 = bias[c + 1];
            *(float2*)(Y + (size_t)r * DM + c) =
                make_float2(acc[mt][nt][0] + b0, acc[mt][nt][1] + b1);
            *(float2*)(Y + (size_t)(r + 8) * DM + c) =
                make_float2(acc[mt][nt][2] + b0, acc[mt][nt][3] + b1);
        }
    }
}

// ---------------------------------------------------------------------------
// Flash attention: QK^T tf32 (fp32 smem pad-68), PV split-bf16:
// O += Phi@Vhi + Phi@Vlo + Plo@Vhi  (lo*lo dropped, ~eps^2).
// Br=Bc=64, 4 warps, cp.async double-buffered K/Vhi/Vlo.
// ---------------------------------------------------------------------------
#define QKLD 68
#define ATTN_SMEM_BYTES ((3 * 64 * QKLD) * 4 + 4 * 64 * 64 * 2)   // 52224+32768

__global__ __launch_bounds__(128) void attn_kernel(
    const float* __restrict__ Q, const float* __restrict__ K,
    const __nv_bfloat16* __restrict__ Vhi, const __nv_bfloat16* __restrict__ Vlo,
    float* __restrict__ O)
{
    extern __shared__ char smraw[];
    float* sQ = (float*)smraw;                        // [64][QKLD]
    float* sK = sQ + 64 * QKLD;                       // [2][64][QKLD]
    __nv_bfloat16* sVh = (__nv_bfloat16*)(sK + 2 * 64 * QKLD);  // [2][4096]
    __nv_bfloat16* sVl = sVh + 2 * 64 * 64;                     // [2][4096]

    const int tid = threadIdx.x, lane = tid & 31, wid = tid >> 5;
    const int qb = (int)gridDim.x - 1 - (int)blockIdx.x;     // long blocks first
    const int h = blockIdx.y, b = blockIdx.z;
    const int q0 = qb * 64;
    const size_t headoff = (size_t)b * LL * DM + (size_t)h * DH;

    const uint32_t sVhu[2] = { smem_u32(sVh), smem_u32(sVh + 64 * 64) };
    const uint32_t sVlu[2] = { smem_u32(sVl), smem_u32(sVl + 64 * 64) };
#define SWA(base, r, c) ((base) + (uint32_t)(r) * 128u + (uint32_t)(((c) ^ ((r) & 7)) << 4))

#pragma unroll
    for (int j = 0; j < 8; ++j) {
        int ci = tid + j * 128;
        int r = ci >> 4, c = ci & 15;
        cp16(smem_u32(sQ + r * QKLD + c * 4), Q + headoff + (size_t)(q0 + r) * DM + c * 4);
    }
    auto loadKV = [&](int kt, int st) {
        const int kv0 = kt * 64;
        float* ks = sK + st * 64 * QKLD;
#pragma unroll
        for (int j = 0; j < 8; ++j) {
            int ci = tid + j * 128;
            int r = ci >> 4, c = ci & 15;
            cp16(smem_u32(ks + r * QKLD + c * 4), K + headoff + (size_t)(kv0 + r) * DM + c * 4);
        }
#pragma unroll
        for (int j = 0; j < 4; ++j) {
            int ci = tid + j * 128;
            int r = ci >> 3, c = ci & 7;
            cp16(SWA(sVhu[st], r, c), Vhi + headoff + (size_t)(kv0 + r) * DM + c * 8);
            cp16(SWA(sVlu[st], r, c), Vlo + headoff + (size_t)(kv0 + r) * DM + c * 8);
        }
    };
    loadKV(0, 0);
    cp_commit();

    const int NT = min(qb + 1, PAD_TILES);

    float o[8][4];
#pragma unroll
    for (int i = 0; i < 8; i++)
#pragma unroll
        for (int r = 0; r < 4; r++) o[i][r] = 0.f;
    float m_lo = -1e30f, m_hi = -1e30f, l_lo = 0.f, l_hi = 0.f;
    uint32_t qa[8][4];

    for (int kt = 0; kt < NT; ++kt) {
        const int st = kt & 1;
        if (kt + 1 < NT) { loadKV(kt + 1, st ^ 1); cp_commit(); cp_wait<1>(); }
        else             { cp_wait<0>(); }
        __syncthreads();

        if (kt == 0) {
#pragma unroll
            for (int ks = 0; ks < 8; ++ks) {
                const float* p = sQ + (size_t)(wid * 16 + (lane >> 2)) * QKLD + ks * 8 + (lane & 3);
                qa[ks][0] = f2tf(p[0]);        qa[ks][1] = f2tf(p[8 * QKLD]);
                qa[ks][2] = f2tf(p[4]);        qa[ks][3] = f2tf(p[8 * QKLD + 4]);
            }
        }

        // ---- S = Q @ K^T (tf32) ----
        float s[8][4];
#pragma unroll
        for (int i = 0; i < 8; i++)
#pragma unroll
            for (int r = 0; r < 4; r++) s[i][r] = 0.f;
        const float* ksm = sK + st * 64 * QKLD;
#pragma unroll
        for (int ks = 0; ks < 8; ++ks) {
#pragma unroll
            for (int p = 0; p < 8; ++p) {
                const float* kp = ksm + (size_t)(p * 8 + (lane >> 2)) * QKLD + ks * 8 + (lane & 3);
                uint32_t bfr[2] = { f2tf(kp[0]), f2tf(kp[4]) };
                mma_tf32(s[p], qa[ks], bfr);
            }
        }
#pragma unroll
        for (int nt = 0; nt < 8; ++nt)
#pragma unroll
            for (int r = 0; r < 4; r++) s[nt][r] *= SCALE2;

        if (kt == qb) {  // causal mask, diagonal tile only
            const int lr = wid * 16 + (lane >> 2);
#pragma unroll
            for (int nt = 0; nt < 8; ++nt) {
                const int lc = nt * 8 + (lane & 3) * 2;
                if (lc     > lr)     s[nt][0] = -1e30f;
                if (lc + 1 > lr)     s[nt][1] = -1e30f;
                if (lc     > lr + 8) s[nt][2] = -1e30f;
                if (lc + 1 > lr + 8) s[nt][3] = -1e30f;
            }
        }

        // ---- online softmax (log2 domain) ----
        float tl = -1e30f, th = -1e30f;
#pragma unroll
        for (int nt = 0; nt < 8; ++nt) {
            tl = fmaxf(tl, fmaxf(s[nt][0], s[nt][1]));
            th = fmaxf(th, fmaxf(s[nt][2], s[nt][3]));
        }
        tl = fmaxf(tl, __shfl_xor_sync(~0u, tl, 1)); tl = fmaxf(tl, __shfl_xor_sync(~0u, tl, 2));
        th = fmaxf(th, __shfl_xor_sync(~0u, th, 1)); th = fmaxf(th, __shfl_xor_sync(~0u, th, 2));

        const float mn_lo = fmaxf(m_lo, tl), mn_hi = fmaxf(m_hi, th);
        const float cor_lo = ex2(m_lo - mn_lo), cor_hi = ex2(m_hi - mn_hi);
        m_lo = mn_lo; m_hi = mn_hi;
        l_lo *= cor_lo; l_hi *= cor_hi;
#pragma unroll
        for (int nt = 0; nt < 8; ++nt) {
            o[nt][0] *= cor_lo; o[nt][1] *= cor_lo;
            o[nt][2] *= cor_hi; o[nt][3] *= cor_hi;
        }

        uint32_t pa[4][4], pl[4][4];
#pragma unroll
        for (int nt = 0; nt < 8; ++nt) {
            const float p0 = ex2(s[nt][0] - m_lo), p1 = ex2(s[nt][1] - m_lo);
            const float p2 = ex2(s[nt][2] - m_hi), p3 = ex2(s[nt][3] - m_hi);
            l_lo += p0 + p1; l_hi += p2 + p3;
            const int j = nt >> 1;
            if ((nt & 1) == 0) {
                pa[j][0] = pack_split(p0, p1, pl[j][0]);
                pa[j][1] = pack_split(p2, p3, pl[j][1]);
            } else {
                pa[j][2] = pack_split(p0, p1, pl[j][2]);
                pa[j][3] = pack_split(p2, p3, pl[j][3]);
            }
        }

        // ---- O += Phi@Vhi + Plo@Vhi + Phi@Vlo ----
#pragma unroll
        for (int j = 0; j < 4; ++j) {
            uint32_t vb[4][4];
#pragma unroll
            for (int dp = 0; dp < 4; ++dp) {
                int rr = j * 16 + ((lane >> 3) & 1) * 8 + (lane & 7);
                int cc = dp * 2 + (lane >> 4);
                ldsm4t(vb[dp], SWA(sVhu[st], rr, cc));
            }
#pragma unroll
            for (int dp = 0; dp < 4; ++dp) {
                uint32_t b0[2] = { vb[dp][0], vb[dp][1] };
                uint32_t b1[2] = { vb[dp][2], vb[dp][3] };
                mma_bf16(o[2 * dp],     pa[j], b0);
                mma_bf16(o[2 * dp + 1], pa[j], b1);
                mma_bf16(o[2 * dp],     pl[j], b0);
                mma_bf16(o[2 * dp + 1], pl[j], b1);
            }
#pragma unroll
            for (int dp = 0; dp < 4; ++dp) {
                int rr = j * 16 + ((lane >> 3) & 1) * 8 + (lane & 7);
                int cc = dp * 2 + (lane >> 4);
                ldsm4t(vb[dp], SWA(sVlu[st], rr, cc));
            }
#pragma unroll
            for (int dp = 0; dp < 4; ++dp) {
                uint32_t b0[2] = { vb[dp][0], vb[dp][1] };
                uint32_t b1[2] = { vb[dp][2], vb[dp][3] };
                mma_bf16(o[2 * dp],     pa[j], b0);
                mma_bf16(o[2 * dp + 1], pa[j], b1);
            }
        }
        __syncthreads();
    }

    l_lo += __shfl_xor_sync(~0u, l_lo, 1); l_lo += __shfl_xor_sync(~0u, l_lo, 2);
    l_hi += __shfl_xor_sync(~0u, l_hi, 1); l_hi += __shfl_xor_sync(~0u, l_hi, 2);
    const float inv_lo = 1.f / l_lo, inv_hi = 1.f / l_hi;

    const int r_lo = q0 + wid * 16 + (lane >> 2);
#pragma unroll
    for (int nt = 0; nt < 8; ++nt) {
        const int col = nt * 8 + (lane & 3) * 2;
        const size_t base = headoff + (size_t)r_lo * DM + col;
        *(float2*)(O + base)          = make_float2(o[nt][0] * inv_lo, o[nt][1] * inv_lo);
        *(float2*)(O + base + 8 * DM) = make_float2(o[nt][2] * inv_hi, o[nt][3] * inv_hi);
    }
#undef SWA
}

// ---------------------------------------------------------------------------
extern "C" void kernel_launch(void* const* d_in, const int* in_sizes, int n_in,
                              void* d_out, int out_size)
{
    const float* X  = (const float*)d_in[0];
    const float* Wq = (const float*)d_in[1];
    const float* bq = (const float*)d_in[2];
    const float* Wk = (const float*)d_in[3];
    const float* bk = (const float*)d_in[4];
    const float* Wv = (const float*)d_in[5];
    const float* bv = (const float*)d_in[6];
    const float* Wo = (const float*)d_in[7];
    const float* bo = (const float*)d_in[8];
    float* out = (float*)d_out;

    float *Qp, *Kp, *Cp; __nv_bfloat16 *Vh, *Vl;
    cudaGetSymbolAddress((void**)&Qp, g_Q);
    cudaGetSymbolAddress((void**)&Kp, g_K);
    cudaGetSymbolAddress((void**)&Vh, g_Vhi);
    cudaGetSymbolAddress((void**)&Vl, g_Vlo);
    cudaGetSymbolAddress((void**)&Cp, g_C);

    cudaFuncSetAttribute(qkv_gemm,    cudaFuncAttributeMaxDynamicSharedMemorySize, GEMM_SMEM_BYTES);
    cudaFuncSetAttribute(out_gemm,    cudaFuncAttributeMaxDynamicSharedMemorySize, GEMM_SMEM_BYTES);
    cudaFuncSetAttribute(attn_kernel, cudaFuncAttributeMaxDynamicSharedMemorySize, ATTN_SMEM_BYTES);

    dim3 gq(DM / 128, MROWS / 128, 3);   // (8, 32, 3)
    qkv_gemm<<<gq, 256, GEMM_SMEM_BYTES>>>(X, Wq, bq, Wk, bk, Wv, bv, Qp, Kp, Vh, Vl);

    dim3 ag(LL / 64, NH, BB);            // (32, 16, 2)
    attn_kernel<<<ag, 128, ATTN_SMEM_BYTES>>>(Qp, Kp, Vh, Vl, Cp);

    dim3 gg(DM / 128, MROWS / 128);      // (8, 32)
    out_gemm<<<gg, 256, GEMM_SMEM_BYTES>>>(Cp, Wo, bo, out);
}

// round 5
// speedup vs baseline: 6.0436x; 1.2778x over previous
#include <cuda_runtime.h>
#include <cuda_bf16.h>
#include <cuda_fp16.h>
#include <stdint.h>

// B=2, L=2048, H=16, Dh=64, D=1024
#define BB 2
#define LL 2048
#define NH 16
#define DH 64
#define DM 1024
#define MROWS (BB * LL)
#define PAD_TILES 28                   // keys >= 1792 masked; 1792/64
#define SCALE2 0.18033688011112042f    // (1/8) * log2(e)

// Scratch (__device__ globals)
__device__ float  g_Xr[(size_t)MROWS * DM];      // tf32-rounded X
__device__ float  g_Wr[(size_t)4 * DM * DM];     // tf32-rounded Wq|Wk|Wv|Wo
__device__ __half g_Qh[(size_t)MROWS * DM];
__device__ __half g_Kh[(size_t)MROWS * DM];
__device__ __half g_Vh[(size_t)MROWS * DM];
__device__ float  g_C[(size_t)MROWS * DM];       // attn out, tf32-rounded

// ---------------- PTX helpers ----------------
__device__ __forceinline__ uint32_t smem_u32(const void* p) {
    return (uint32_t)__cvta_generic_to_shared(p);
}
__device__ __forceinline__ void cp16(uint32_t s, const void* g) {
    asm volatile("cp.async.cg.shared.global [%0], [%1], 16;" :: "r"(s), "l"(g));
}
__device__ __forceinline__ void cp_commit() {
    asm volatile("cp.async.commit_group;" ::: "memory");
}
template <int N> __device__ __forceinline__ void cp_wait() {
    asm volatile("cp.async.wait_group %0;" :: "n"(N) : "memory");
}
__device__ __forceinline__ uint32_t f2tf(float x) {
    uint32_t u; asm("cvt.rna.tf32.f32 %0, %1;" : "=r"(u) : "f"(x)); return u;
}
__device__ __forceinline__ float ex2(float x) {
    float r; asm("ex2.approx.f32 %0, %1;" : "=f"(r) : "f"(x)); return r;
}
__device__ __forceinline__ void mma_tf32(float* d, const uint32_t* a, const uint32_t* b) {
    asm volatile("mma.sync.aligned.m16n8k8.row.col.f32.tf32.tf32.f32 "
        "{%0,%1,%2,%3},{%4,%5,%6,%7},{%8,%9},{%0,%1,%2,%3};"
        : "+f"(d[0]), "+f"(d[1]), "+f"(d[2]), "+f"(d[3])
        : "r"(a[0]), "r"(a[1]), "r"(a[2]), "r"(a[3]), "r"(b[0]), "r"(b[1]));
}
__device__ __forceinline__ void mma_f16(float* d, const uint32_t* a, const uint32_t* b) {
    asm volatile("mma.sync.aligned.m16n8k16.row.col.f32.f16.f16.f32 "
        "{%0,%1,%2,%3},{%4,%5,%6,%7},{%8,%9},{%0,%1,%2,%3};"
        : "+f"(d[0]), "+f"(d[1]), "+f"(d[2]), "+f"(d[3])
        : "r"(a[0]), "r"(a[1]), "r"(a[2]), "r"(a[3]), "r"(b[0]), "r"(b[1]));
}
__device__ __forceinline__ void ldsm4(uint32_t* r, uint32_t a) {
    asm volatile("ldmatrix.sync.aligned.m8n8.x4.shared.b16 {%0,%1,%2,%3},[%4];"
                 : "=r"(r[0]), "=r"(r[1]), "=r"(r[2]), "=r"(r[3]) : "r"(a));
}
__device__ __forceinline__ void ldsm4t(uint32_t* r, uint32_t a) {
    asm volatile("ldmatrix.sync.aligned.m8n8.x4.trans.shared.b16 {%0,%1,%2,%3},[%4];"
                 : "=r"(r[0]), "=r"(r[1]), "=r"(r[2]), "=r"(r[3]) : "r"(a));
}
__device__ __forceinline__ uint32_t pack_h2(float a, float b) {
    __half2 h = __floats2half2_rn(a, b);
    return *(uint32_t*)&h;
}

// ---------------------------------------------------------------------------
// Prep: round fp32 -> tf32 (rna), stored as fp32 bits with low mantissa zeroed.
// ---------------------------------------------------------------------------
__global__ __launch_bounds__(256) void round_tf32(
    const float* __restrict__ in, float* __restrict__ out, int n4)
{
    int i = blockIdx.x * blockDim.x + threadIdx.x;
    if (i < n4) {
        float4 v = ((const float4*)in)[i];
        v.x = __uint_as_float(f2tf(v.x));
        v.y = __uint_as_float(f2tf(v.y));
        v.z = __uint_as_float(f2tf(v.z));
        v.w = __uint_as_float(f2tf(v.w));
        ((float4*)out)[i] = v;
    }
}

// ---------------------------------------------------------------------------
// tf32 GEMM core (pre-rounded inputs; NO cvt in the mainloop).
// 128x128 tile, BK=32, 256 thr (8 warps 2x4), warp 64x32, double buffer.
// ---------------------------------------------------------------------------
#define GBK 32
#define GLD 36
#define GEMM_SMEM_BYTES (2 * 2 * 128 * GLD * 4)

#define GEMM_MAIN(APTR, WPTR)                                                   \
    float* As = dsm;                                                            \
    float* Bs = dsm + 2 * 128 * GLD;                                            \
    const int lane = tid & 31, wid = tid >> 5;                                  \
    const int wm = wid >> 2, wn = wid & 3;                                      \
    float acc[4][4][4];                                                         \
    _Pragma("unroll") for (int i = 0; i < 4; i++)                               \
    _Pragma("unroll") for (int j = 0; j < 4; j++)                               \
    _Pragma("unroll") for (int r = 0; r < 4; r++) acc[i][j][r] = 0.f;           \
    auto load_tiles = [&](int kt, int st) {                                     \
        const int k0 = kt * GBK;                                                \
        float* as = As + st * 128 * GLD;                                        \
        float* bs = Bs + st * 128 * GLD;                                        \
        _Pragma("unroll") for (int j = 0; j < 4; j++) {                         \
            int ci = tid + j * 256;                                             \
            int r = ci >> 3, c = ci & 7;                                        \
            cp16(smem_u32(as + r * GLD + c * 4), (APTR) + (size_t)(row0 + r) * DM + k0 + c * 4); \
            cp16(smem_u32(bs + r * GLD + c * 4), (WPTR) + (size_t)(col0 + r) * DM + k0 + c * 4); \
        }                                                                       \
    };                                                                          \
    load_tiles(0, 0);                                                           \
    cp_commit();                                                                \
    const int NTk = DM / GBK;                                                   \
    for (int kt = 0; kt < NTk; ++kt) {                                          \
        const int st = kt & 1;                                                  \
        if (kt + 1 < NTk) { load_tiles(kt + 1, st ^ 1); cp_commit(); cp_wait<1>(); } \
        else              { cp_wait<0>(); }                                     \
        __syncthreads();                                                        \
        const float* as = As + st * 128 * GLD;                                  \
        const float* bs = Bs + st * 128 * GLD;                                  \
        _Pragma("unroll") for (int ks = 0; ks < 4; ++ks) {                      \
            const int kk = ks * 8;                                              \
            uint32_t af[4][4], bf[4][2];                                        \
            _Pragma("unroll") for (int mt = 0; mt < 4; ++mt) {                  \
                const float* p = as + (size_t)(wm * 64 + mt * 16 + (lane >> 2)) * GLD + kk + (lane & 3); \
                af[mt][0] = __float_as_uint(p[0]);                              \
                af[mt][1] = __float_as_uint(p[8 * GLD]);                        \
                af[mt][2] = __float_as_uint(p[4]);                              \
                af[mt][3] = __float_as_uint(p[8 * GLD + 4]);                    \
            }                                                                   \
            _Pragma("unroll") for (int nt = 0; nt < 4; ++nt) {                  \
                const float* p = bs + (size_t)(wn * 32 + nt * 8 + (lane >> 2)) * GLD + kk + (lane & 3); \
                bf[nt][0] = __float_as_uint(p[0]);                              \
                bf[nt][1] = __float_as_uint(p[4]);                              \
            }                                                                   \
            _Pragma("unroll") for (int mt = 0; mt < 4; ++mt)                    \
            _Pragma("unroll") for (int nt = 0; nt < 4; ++nt)                    \
                mma_tf32(acc[mt][nt], af[mt], bf[nt]);                          \
        }                                                                       \
        __syncthreads();                                                        \
    }

// QKV fused projection: blockIdx.z selects {Q,K,V}; outputs fp16.
__global__ __launch_bounds__(256) void qkv_gemm(
    const float* __restrict__ X, const float* __restrict__ Wall,
    const float* __restrict__ bq, const float* __restrict__ bk,
    const float* __restrict__ bv,
    __half* __restrict__ Qh, __half* __restrict__ Kh, __half* __restrict__ Vh)
{
    extern __shared__ float dsm[];
    const int tid = threadIdx.x;
    const int row0 = blockIdx.y * 128, col0 = blockIdx.x * 128;
    const int z = blockIdx.z;
    const float* W    = Wall + (size_t)z * DM * DM;
    const float* bias = (z == 0) ? bq : (z == 1) ? bk : bv;
    __half* out       = (z == 0) ? Qh : (z == 1) ? Kh : Vh;

    GEMM_MAIN(X, W)

#pragma unroll
    for (int mt = 0; mt < 4; ++mt) {
        const int r = row0 + wm * 64 + mt * 16 + (lane >> 2);
#pragma unroll
        for (int nt = 0; nt < 4; ++nt) {
            const int c = col0 + wn * 32 + nt * 8 + (lane & 3) * 2;
            const float b0 = bias[c], b1 = bias[c + 1];
            *(uint32_t*)(out + (size_t)r * DM + c) =
                pack_h2(acc[mt][nt][0] + b0, acc[mt][nt][1] + b1);
            *(uint32_t*)(out + (size_t)(r + 8) * DM + c) =
                pack_h2(acc[mt][nt][2] + b0, acc[mt][nt][3] + b1);
        }
    }
}

// Output projection: fp32 out + bias.
__global__ __launch_bounds__(256) void out_gemm(
    const float* __restrict__ A, const float* __restrict__ W,
    const float* __restrict__ bias, float* __restrict__ Y)
{
    extern __shared__ float dsm[];
    const int tid = threadIdx.x;
    const int row0 = blockIdx.y * 128, col0 = blockIdx.x * 128;

    GEMM_MAIN(A, W)

#pragma unroll
    for (int mt = 0; mt < 4; ++mt) {
        const int r = row0 + wm * 64 + mt * 16 + (lane >> 2);
#pragma unroll
        for (int nt = 0; nt < 4; ++nt) {
            const int c = col0 + wn * 32 + nt * 8 + (lane & 3) * 2;
            const float b0 = bias[c], b1 = bias[c + 1];
            *(float2*)(Y + (size_t)r * DM + c) =
                make_float2(acc[mt][nt][0] + b0, acc[mt][nt][1] + b1);
            *(float2*)(Y + (size_t)(r + 8) * DM + c) =
                make_float2(acc[mt][nt][2] + b0, acc[mt][nt][3] + b1);
        }
    }
}

// ---------------------------------------------------------------------------
// Flash attention, all-fp16 operands, fp32 accum. Br=Bc=64, 4 warps.
// QK^T: ldmatrix(K) + mma.f16 (32/tile). PV: ldmatrix.trans(V) + mma.f16 (32/tile).
// ---------------------------------------------------------------------------
__global__ __launch_bounds__(128) void attn_kernel(
    const __half* __restrict__ Q, const __half* __restrict__ K,
    const __half* __restrict__ V, float* __restrict__ O)
{
    __shared__ __align__(1024) __half sQ[64 * 64];
    __shared__ __align__(1024) __half sK[2][64 * 64];
    __shared__ __align__(1024) __half sV[2][64 * 64];

    const int tid = threadIdx.x, lane = tid & 31, wid = tid >> 5;
    const int qb = (int)gridDim.x - 1 - (int)blockIdx.x;     // long blocks first
    const int h = blockIdx.y, b = blockIdx.z;
    const int q0 = qb * 64;
    const size_t headoff = (size_t)b * LL * DM + (size_t)h * DH;

    const uint32_t sQu = smem_u32(sQ);
    const uint32_t sKu[2] = { smem_u32(sK[0]), smem_u32(sK[1]) };
    const uint32_t sVu[2] = { smem_u32(sV[0]), smem_u32(sV[1]) };
#define SWA(base, r, c) ((base) + (uint32_t)(r) * 128u + (uint32_t)(((c) ^ ((r) & 7)) << 4))

    // Q tile: 64 rows x 8 chunks(16B)
#pragma unroll
    for (int j = 0; j < 4; ++j) {
        int ci = tid + j * 128;
        int r = ci >> 3, c = ci & 7;
        cp16(SWA(sQu, r, c), Q + headoff + (size_t)(q0 + r) * DM + c * 8);
    }
    auto loadKV = [&](int kt, int st) {
        const int kv0 = kt * 64;
#pragma unroll
        for (int j = 0; j < 4; ++j) {
            int ci = tid + j * 128;
            int r = ci >> 3, c = ci & 7;
            const size_t go = headoff + (size_t)(kv0 + r) * DM + c * 8;
            cp16(SWA(sKu[st], r, c), K + go);
            cp16(SWA(sVu[st], r, c), V + go);
        }
    };
    loadKV(0, 0);
    cp_commit();

    const int NT = min(qb + 1, PAD_TILES);

    float o[8][4];
#pragma unroll
    for (int i = 0; i < 8; i++)
#pragma unroll
        for (int r = 0; r < 4; r++) o[i][r] = 0.f;
    float m_lo = -1e30f, m_hi = -1e30f, l_lo = 0.f, l_hi = 0.f;
    uint32_t qa[4][4];

    for (int kt = 0; kt < NT; ++kt) {
        const int st = kt & 1;
        if (kt + 1 < NT) { loadKV(kt + 1, st ^ 1); cp_commit(); cp_wait<1>(); }
        else             { cp_wait<0>(); }
        __syncthreads();

        if (kt == 0) {   // Q a-frags once: 4 k16-steps
#pragma unroll
            for (int ks = 0; ks < 4; ++ks) {
                int rr = wid * 16 + ((lane >> 3) & 1) * 8 + (lane & 7);
                int cc = ks * 2 + (lane >> 4);
                ldsm4(qa[ks], SWA(sQu, rr, cc));
            }
        }

        // ---- S = Q @ K^T (fp16) ----
        float s[8][4];
#pragma unroll
        for (int i = 0; i < 8; i++)
#pragma unroll
            for (int r = 0; r < 4; r++) s[i][r] = 0.f;
#pragma unroll
        for (int ks = 0; ks < 4; ++ks) {
#pragma unroll
            for (int p2 = 0; p2 < 4; ++p2) {
                uint32_t kb[4];
                int rr = p2 * 16 + ((lane >> 3) & 1) * 8 + (lane & 7);
                int cc = ks * 2 + (lane >> 4);
                ldsm4(kb, SWA(sKu[st], rr, cc));
                uint32_t b0[2] = { kb[0], kb[2] };
                uint32_t b1[2] = { kb[1], kb[3] };
                mma_f16(s[2 * p2],     qa[ks], b0);
                mma_f16(s[2 * p2 + 1], qa[ks], b1);
            }
        }
#pragma unroll
        for (int nt = 0; nt < 8; ++nt)
#pragma unroll
            for (int r = 0; r < 4; r++) s[nt][r] *= SCALE2;

        if (kt == qb) {  // causal mask, diagonal tile only
            const int lr = wid * 16 + (lane >> 2);
#pragma unroll
            for (int nt = 0; nt < 8; ++nt) {
                const int lc = nt * 8 + (lane & 3) * 2;
                if (lc     > lr)     s[nt][0] = -1e30f;
                if (lc + 1 > lr)     s[nt][1] = -1e30f;
                if (lc     > lr + 8) s[nt][2] = -1e30f;
                if (lc + 1 > lr + 8) s[nt][3] = -1e30f;
            }
        }

        // ---- online softmax (log2 domain) ----
        float tl = -1e30f, th = -1e30f;
#pragma unroll
        for (int nt = 0; nt < 8; ++nt) {
            tl = fmaxf(tl, fmaxf(s[nt][0], s[nt][1]));
            th = fmaxf(th, fmaxf(s[nt][2], s[nt][3]));
        }
        tl = fmaxf(tl, __shfl_xor_sync(~0u, tl, 1)); tl = fmaxf(tl, __shfl_xor_sync(~0u, tl, 2));
        th = fmaxf(th, __shfl_xor_sync(~0u, th, 1)); th = fmaxf(th, __shfl_xor_sync(~0u, th, 2));

        const float mn_lo = fmaxf(m_lo, tl), mn_hi = fmaxf(m_hi, th);
        const float cor_lo = ex2(m_lo - mn_lo), cor_hi = ex2(m_hi - mn_hi);
        m_lo = mn_lo; m_hi = mn_hi;
        l_lo *= cor_lo; l_hi *= cor_hi;
#pragma unroll
        for (int nt = 0; nt < 8; ++nt) {
            o[nt][0] *= cor_lo; o[nt][1] *= cor_lo;
            o[nt][2] *= cor_hi; o[nt][3] *= cor_hi;
        }

        uint32_t pa[4][4];
#pragma unroll
        for (int nt = 0; nt < 8; ++nt) {
            const float p0 = ex2(s[nt][0] - m_lo), p1 = ex2(s[nt][1] - m_lo);
            const float p2 = ex2(s[nt][2] - m_hi), p3 = ex2(s[nt][3] - m_hi);
            l_lo += p0 + p1; l_hi += p2 + p3;
            const int j = nt >> 1;
            if ((nt & 1) == 0) { pa[j][0] = pack_h2(p0, p1); pa[j][1] = pack_h2(p2, p3); }
            else               { pa[j][2] = pack_h2(p0, p1); pa[j][3] = pack_h2(p2, p3); }
        }

        // ---- O += P @ V (fp16) ----
#pragma unroll
        for (int j = 0; j < 4; ++j) {
            uint32_t vb[4][4];
#pragma unroll
            for (int dp = 0; dp < 4; ++dp) {
                int rr = j * 16 + ((lane >> 3) & 1) * 8 + (lane & 7);
                int cc = dp * 2 + (lane >> 4);
                ldsm4t(vb[dp], SWA(sVu[st], rr, cc));
            }
#pragma unroll
            for (int dp = 0; dp < 4; ++dp) {
                uint32_t b0[2] = { vb[dp][0], vb[dp][1] };
                uint32_t b1[2] = { vb[dp][2], vb[dp][3] };
                mma_f16(o[2 * dp],     pa[j], b0);
                mma_f16(o[2 * dp + 1], pa[j], b1);
            }
        }
        __syncthreads();
    }

    l_lo += __shfl_xor_sync(~0u, l_lo, 1); l_lo += __shfl_xor_sync(~0u, l_lo, 2);
    l_hi += __shfl_xor_sync(~0u, l_hi, 1); l_hi += __shfl_xor_sync(~0u, l_hi, 2);
    const float inv_lo = 1.f / l_lo, inv_hi = 1.f / l_hi;

    // write C pre-rounded to tf32 so out_gemm consumes raw bits
    const int r_lo = q0 + wid * 16 + (lane >> 2);
#pragma unroll
    for (int nt = 0; nt < 8; ++nt) {
        const int col = nt * 8 + (lane & 3) * 2;
        const size_t base = headoff + (size_t)r_lo * DM + col;
        *(float2*)(O + base) = make_float2(
            __uint_as_float(f2tf(o[nt][0] * inv_lo)),
            __uint_as_float(f2tf(o[nt][1] * inv_lo)));
        *(float2*)(O + base + 8 * DM) = make_float2(
            __uint_as_float(f2tf(o[nt][2] * inv_hi)),
            __uint_as_float(f2tf(o[nt][3] * inv_hi)));
    }
#undef SWA
}

// ---------------------------------------------------------------------------
extern "C" void kernel_launch(void* const* d_in, const int* in_sizes, int n_in,
                              void* d_out, int out_size)
{
    const float* X  = (const float*)d_in[0];
    const float* Wq = (const float*)d_in[1];
    const float* bq = (const float*)d_in[2];
    const float* Wk = (const float*)d_in[3];
    const float* bk = (const float*)d_in[4];
    const float* Wv = (const float*)d_in[5];
    const float* bv = (const float*)d_in[6];
    const float* Wo = (const float*)d_in[7];
    const float* bo = (const float*)d_in[8];
    float* out = (float*)d_out;

    float *Xr, *Wr, *Cp; __half *Qh, *Kh, *Vh;
    cudaGetSymbolAddress((void**)&Xr, g_Xr);
    cudaGetSymbolAddress((void**)&Wr, g_Wr);
    cudaGetSymbolAddress((void**)&Qh, g_Qh);
    cudaGetSymbolAddress((void**)&Kh, g_Kh);
    cudaGetSymbolAddress((void**)&Vh, g_Vh);
    cudaGetSymbolAddress((void**)&Cp, g_C);

    cudaFuncSetAttribute(qkv_gemm, cudaFuncAttributeMaxDynamicSharedMemorySize, GEMM_SMEM_BYTES);
    cudaFuncSetAttribute(out_gemm, cudaFuncAttributeMaxDynamicSharedMemorySize, GEMM_SMEM_BYTES);

    // prep: tf32-round X and all weights
    const int NX4 = MROWS * DM / 4, NW4 = DM * DM / 4;
    round_tf32<<<NX4 / 256, 256>>>(X, Xr, NX4);
    round_tf32<<<NW4 / 256, 256>>>(Wq, Wr + 0 * (size_t)DM * DM, NW4);
    round_tf32<<<NW4 / 256, 256>>>(Wk, Wr + 1 * (size_t)DM * DM, NW4);
    round_tf32<<<NW4 / 256, 256>>>(Wv, Wr + 2 * (size_t)DM * DM, NW4);
    round_tf32<<<NW4 / 256, 256>>>(Wo, Wr + 3 * (size_t)DM * DM, NW4);

    dim3 gq(DM / 128, MROWS / 128, 3);   // (8, 32, 3)
    qkv_gemm<<<gq, 256, GEMM_SMEM_BYTES>>>(Xr, Wr, bq, bk, bv, Qh, Kh, Vh);

    dim3 ag(LL / 64, NH, BB);            // (32, 16, 2)
    attn_kernel<<<ag, 128>>>(Qh, Kh, Vh, Cp);

    dim3 gg(DM / 128, MROWS / 128);      // (8, 32)
    out_gemm<<<gg, 256, GEMM_SMEM_BYTES>>>(Cp, Wr + 3 * (size_t)DM * DM, bo, out);
}

// round 6
// speedup vs baseline: 6.4371x; 1.0651x over previous
#include <cuda_runtime.h>
#include <cuda_bf16.h>
#include <cuda_fp16.h>
#include <stdint.h>

// B=2, L=2048, H=16, Dh=64, D=1024
#define BB 2
#define LL 2048
#define NH 16
#define DH 64
#define DM 1024
#define MROWS (BB * LL)
#define PAD_TILES 28                   // keys >= 1792 masked; 1792/64
#define SCALE2 0.18033688011112042f    // (1/8) * log2(e)

// Scratch (__device__ globals)
__device__ float  g_Xr[(size_t)MROWS * DM];      // tf32-rounded X
__device__ float  g_Wr[(size_t)4 * DM * DM];     // tf32-rounded Wq|Wk|Wv|Wo
__device__ __half g_Qh[(size_t)MROWS * DM];
__device__ __half g_Kh[(size_t)MROWS * DM];
__device__ __half g_Vh[(size_t)MROWS * DM];
__device__ float  g_C[(size_t)MROWS * DM];       // attn out, tf32-rounded

// ---------------- PTX helpers ----------------
__device__ __forceinline__ uint32_t smem_u32(const void* p) {
    return (uint32_t)__cvta_generic_to_shared(p);
}
__device__ __forceinline__ void cp16(uint32_t s, const void* g) {
    asm volatile("cp.async.cg.shared.global [%0], [%1], 16;" :: "r"(s), "l"(g));
}
__device__ __forceinline__ void cp_commit() {
    asm volatile("cp.async.commit_group;" ::: "memory");
}
template <int N> __device__ __forceinline__ void cp_wait() {
    asm volatile("cp.async.wait_group %0;" :: "n"(N) : "memory");
}
__device__ __forceinline__ uint32_t f2tf(float x) {
    uint32_t u; asm("cvt.rna.tf32.f32 %0, %1;" : "=r"(u) : "f"(x)); return u;
}
__device__ __forceinline__ float ex2(float x) {
    float r; asm("ex2.approx.f32 %0, %1;" : "=f"(r) : "f"(x)); return r;
}
__device__ __forceinline__ void mma_tf32(float* d, const uint32_t* a, const uint32_t* b) {
    asm volatile("mma.sync.aligned.m16n8k8.row.col.f32.tf32.tf32.f32 "
        "{%0,%1,%2,%3},{%4,%5,%6,%7},{%8,%9},{%0,%1,%2,%3};"
        : "+f"(d[0]), "+f"(d[1]), "+f"(d[2]), "+f"(d[3])
        : "r"(a[0]), "r"(a[1]), "r"(a[2]), "r"(a[3]), "r"(b[0]), "r"(b[1]));
}
__device__ __forceinline__ void mma_f16(float* d, const uint32_t* a, const uint32_t* b) {
    asm volatile("mma.sync.aligned.m16n8k16.row.col.f32.f16.f16.f32 "
        "{%0,%1,%2,%3},{%4,%5,%6,%7},{%8,%9},{%0,%1,%2,%3};"
        : "+f"(d[0]), "+f"(d[1]), "+f"(d[2]), "+f"(d[3])
        : "r"(a[0]), "r"(a[1]), "r"(a[2]), "r"(a[3]), "r"(b[0]), "r"(b[1]));
}
__device__ __forceinline__ void ldsm4(uint32_t* r, uint32_t a) {
    asm volatile("ldmatrix.sync.aligned.m8n8.x4.shared.b16 {%0,%1,%2,%3},[%4];"
                 : "=r"(r[0]), "=r"(r[1]), "=r"(r[2]), "=r"(r[3]) : "r"(a));
}
__device__ __forceinline__ void ldsm2(uint32_t* r, uint32_t a) {
    asm volatile("ldmatrix.sync.aligned.m8n8.x2.shared.b16 {%0,%1},[%2];"
                 : "=r"(r[0]), "=r"(r[1]) : "r"(a));
}
__device__ __forceinline__ void ldsm4t(uint32_t* r, uint32_t a) {
    asm volatile("ldmatrix.sync.aligned.m8n8.x4.trans.shared.b16 {%0,%1,%2,%3},[%4];"
                 : "=r"(r[0]), "=r"(r[1]), "=r"(r[2]), "=r"(r[3]) : "r"(a));
}
__device__ __forceinline__ uint32_t pack_h2(float a, float b) {
    __half2 h = __floats2half2_rn(a, b);
    return *(uint32_t*)&h;
}

// ---------------------------------------------------------------------------
// Prep (single launch): tf32-round X and all 4 weights.
// ---------------------------------------------------------------------------
#define NX4 (MROWS * DM / 4)
#define NW4 (DM * DM / 4)

__global__ __launch_bounds__(256) void round_all(
    const float* __restrict__ X,
    const float* __restrict__ Wq, const float* __restrict__ Wk,
    const float* __restrict__ Wv, const float* __restrict__ Wo,
    float* __restrict__ Xr, float* __restrict__ Wr)
{
    int i = blockIdx.x * 256 + threadIdx.x;
    const float4* src; float4* dst; int j;
    if (i < NX4) {
        src = (const float4*)X; dst = (float4*)Xr; j = i;
    } else {
        int t = i - NX4;
        int w = t / NW4; j = t - w * NW4;
        src = (const float4*)(w == 0 ? Wq : w == 1 ? Wk : w == 2 ? Wv : Wo);
        dst = (float4*)(Wr + (size_t)w * DM * DM);
    }
    float4 v = src[j];
    v.x = __uint_as_float(f2tf(v.x));
    v.y = __uint_as_float(f2tf(v.y));
    v.z = __uint_as_float(f2tf(v.z));
    v.w = __uint_as_float(f2tf(v.w));
    dst[j] = v;
}

// ---------------------------------------------------------------------------
// tf32 GEMM core (pre-rounded inputs; ldmatrix fragment loads — tf32 frags
// have the exact m8n8.b16 ldmatrix distribution when rows are read as
// 4-float 16B segments). 128x128 tile, BK=32, 256 thr, warp 64x32.
// ---------------------------------------------------------------------------
#define GBK 32
#define GLD 36
#define GEMM_SMEM_BYTES (2 * 2 * 128 * GLD * 4)

#define GEMM_MAIN(APTR, WPTR)                                                   \
    float* As = dsm;                                                            \
    float* Bs = dsm + 2 * 128 * GLD;                                            \
    const int lane = tid & 31, wid = tid >> 5;                                  \
    const int wm = wid >> 2, wn = wid & 3;                                      \
    /* ldmatrix lane->address mapping (A: x4, B: x2) */                         \
    const int a_r = wm * 64 + ((lane >> 3) & 1) * 8 + (lane & 7);               \
    const int a_c = (lane >> 4) * 4;                                            \
    const int b_r = wn * 32 + (lane & 7);                                       \
    const int b_c = ((lane >> 3) & 1) * 4;                                      \
    float acc[4][4][4];                                                         \
    _Pragma("unroll") for (int i = 0; i < 4; i++)                               \
    _Pragma("unroll") for (int j = 0; j < 4; j++)                               \
    _Pragma("unroll") for (int r = 0; r < 4; r++) acc[i][j][r] = 0.f;           \
    auto load_tiles = [&](int kt, int st) {                                     \
        const int k0 = kt * GBK;                                                \
        float* as = As + st * 128 * GLD;                                        \
        float* bs = Bs + st * 128 * GLD;                                        \
        _Pragma("unroll") for (int j = 0; j < 4; j++) {                         \
            int ci = tid + j * 256;                                             \
            int r = ci >> 3, c = ci & 7;                                        \
            cp16(smem_u32(as + r * GLD + c * 4), (APTR) + (size_t)(row0 + r) * DM + k0 + c * 4); \
            cp16(smem_u32(bs + r * GLD + c * 4), (WPTR) + (size_t)(col0 + r) * DM + k0 + c * 4); \
        }                                                                       \
    };                                                                          \
    load_tiles(0, 0);                                                           \
    cp_commit();                                                                \
    const int NTk = DM / GBK;                                                   \
    for (int kt = 0; kt < NTk; ++kt) {                                          \
        const int st = kt & 1;                                                  \
        if (kt + 1 < NTk) { load_tiles(kt + 1, st ^ 1); cp_commit(); cp_wait<1>(); } \
        else              { cp_wait<0>(); }                                     \
        __syncthreads();                                                        \
        const uint32_t asu = smem_u32(As + st * 128 * GLD);                     \
        const uint32_t bsu = smem_u32(Bs + st * 128 * GLD);                     \
        _Pragma("unroll") for (int ks = 0; ks < 4; ++ks) {                      \
            uint32_t af[4][4], bf[4][2];                                        \
            _Pragma("unroll") for (int mt = 0; mt < 4; ++mt)                    \
                ldsm4(af[mt], asu + 4u * ((a_r + mt * 16) * GLD + ks * 8 + a_c)); \
            _Pragma("unroll") for (int nt = 0; nt < 4; ++nt)                    \
                ldsm2(bf[nt], bsu + 4u * ((b_r + nt * 8) * GLD + ks * 8 + b_c)); \
            _Pragma("unroll") for (int mt = 0; mt < 4; ++mt)                    \
            _Pragma("unroll") for (int nt = 0; nt < 4; ++nt)                    \
                mma_tf32(acc[mt][nt], af[mt], bf[nt]);                          \
        }                                                                       \
        __syncthreads();                                                        \
    }

// QKV fused projection: blockIdx.z selects {Q,K,V}; outputs fp16.
__global__ __launch_bounds__(256) void qkv_gemm(
    const float* __restrict__ X, const float* __restrict__ Wall,
    const float* __restrict__ bq, const float* __restrict__ bk,
    const float* __restrict__ bv,
    __half* __restrict__ Qh, __half* __restrict__ Kh, __half* __restrict__ Vh)
{
    extern __shared__ float dsm[];
    const int tid = threadIdx.x;
    const int row0 = blockIdx.y * 128, col0 = blockIdx.x * 128;
    const int z = blockIdx.z;
    const float* W    = Wall + (size_t)z * DM * DM;
    const float* bias = (z == 0) ? bq : (z == 1) ? bk : bv;
    __half* out       = (z == 0) ? Qh : (z == 1) ? Kh : Vh;

    GEMM_MAIN(X, W)

#pragma unroll
    for (int mt = 0; mt < 4; ++mt) {
        const int r = row0 + wm * 64 + mt * 16 + (lane >> 2);
#pragma unroll
        for (int nt = 0; nt < 4; ++nt) {
            const int c = col0 + wn * 32 + nt * 8 + (lane & 3) * 2;
            const float b0 = bias[c], b1 = bias[c + 1];
            *(uint32_t*)(out + (size_t)r * DM + c) =
                pack_h2(acc[mt][nt][0] + b0, acc[mt][nt][1] + b1);
            *(uint32_t*)(out + (size_t)(r + 8) * DM + c) =
                pack_h2(acc[mt][nt][2] + b0, acc[mt][nt][3] + b1);
        }
    }
}

// Output projection: fp32 out + bias.
__global__ __launch_bounds__(256) void out_gemm(
    const float* __restrict__ A, const float* __restrict__ W,
    const float* __restrict__ bias, float* __restrict__ Y)
{
    extern __shared__ float dsm[];
    const int tid = threadIdx.x;
    const int row0 = blockIdx.y * 128, col0 = blockIdx.x * 128;

    GEMM_MAIN(A, W)

#pragma unroll
    for (int mt = 0; mt < 4; ++mt) {
        const int r = row0 + wm * 64 + mt * 16 + (lane >> 2);
#pragma unroll
        for (int nt = 0; nt < 4; ++nt) {
            const int c = col0 + wn * 32 + nt * 8 + (lane & 3) * 2;
            const float b0 = bias[c], b1 = bias[c + 1];
            *(float2*)(Y + (size_t)r * DM + c) =
                make_float2(acc[mt][nt][0] + b0, acc[mt][nt][1] + b1);
            *(float2*)(Y + (size_t)(r + 8) * DM + c) =
                make_float2(acc[mt][nt][2] + b0, acc[mt][nt][3] + b1);
        }
    }
}

// ---------------------------------------------------------------------------
// Flash attention, all-fp16 operands, fp32 accum. Br=Bc=64, 4 warps.
// ---------------------------------------------------------------------------
__global__ __launch_bounds__(128) void attn_kernel(
    const __half* __restrict__ Q, const __half* __restrict__ K,
    const __half* __restrict__ V, float* __restrict__ O)
{
    __shared__ __align__(1024) __half sQ[64 * 64];
    __shared__ __align__(1024) __half sK[2][64 * 64];
    __shared__ __align__(1024) __half sV[2][64 * 64];

    const int tid = threadIdx.x, lane = tid & 31, wid = tid >> 5;
    const int qb = (int)gridDim.x - 1 - (int)blockIdx.x;     // long blocks first
    const int h = blockIdx.y, b = blockIdx.z;
    const int q0 = qb * 64;
    const size_t headoff = (size_t)b * LL * DM + (size_t)h * DH;

    const uint32_t sQu = smem_u32(sQ);
    const uint32_t sKu[2] = { smem_u32(sK[0]), smem_u32(sK[1]) };
    const uint32_t sVu[2] = { smem_u32(sV[0]), smem_u32(sV[1]) };
#define SWA(base, r, c) ((base) + (uint32_t)(r) * 128u + (uint32_t)(((c) ^ ((r) & 7)) << 4))

#pragma unroll
    for (int j = 0; j < 4; ++j) {
        int ci = tid + j * 128;
        int r = ci >> 3, c = ci & 7;
        cp16(SWA(sQu, r, c), Q + headoff + (size_t)(q0 + r) * DM + c * 8);
    }
    auto loadKV = [&](int kt, int st) {
        const int kv0 = kt * 64;
#pragma unroll
        for (int j = 0; j < 4; ++j) {
            int ci = tid + j * 128;
            int r = ci >> 3, c = ci & 7;
            const size_t go = headoff + (size_t)(kv0 + r) * DM + c * 8;
            cp16(SWA(sKu[st], r, c), K + go);
            cp16(SWA(sVu[st], r, c), V + go);
        }
    };
    loadKV(0, 0);
    cp_commit();

    const int NT = min(qb + 1, PAD_TILES);

    float o[8][4];
#pragma unroll
    for (int i = 0; i < 8; i++)
#pragma unroll
        for (int r = 0; r < 4; r++) o[i][r] = 0.f;
    float m_lo = -1e30f, m_hi = -1e30f, l_lo = 0.f, l_hi = 0.f;
    uint32_t qa[4][4];

    for (int kt = 0; kt < NT; ++kt) {
        const int st = kt & 1;
        if (kt + 1 < NT) { loadKV(kt + 1, st ^ 1); cp_commit(); cp_wait<1>(); }
        else             { cp_wait<0>(); }
        __syncthreads();

        if (kt == 0) {
#pragma unroll
            for (int ks = 0; ks < 4; ++ks) {
                int rr = wid * 16 + ((lane >> 3) & 1) * 8 + (lane & 7);
                int cc = ks * 2 + (lane >> 4);
                ldsm4(qa[ks], SWA(sQu, rr, cc));
            }
        }

        // ---- S = Q @ K^T (fp16) ----
        float s[8][4];
#pragma unroll
        for (int i = 0; i < 8; i++)
#pragma unroll
            for (int r = 0; r < 4; r++) s[i][r] = 0.f;
#pragma unroll
        for (int ks = 0; ks < 4; ++ks) {
#pragma unroll
            for (int p2 = 0; p2 < 4; ++p2) {
                uint32_t kb[4];
                int rr = p2 * 16 + ((lane >> 3) & 1) * 8 + (lane & 7);
                int cc = ks * 2 + (lane >> 4);
                ldsm4(kb, SWA(sKu[st], rr, cc));
                uint32_t b0[2] = { kb[0], kb[2] };
                uint32_t b1[2] = { kb[1], kb[3] };
                mma_f16(s[2 * p2],     qa[ks], b0);
                mma_f16(s[2 * p2 + 1], qa[ks], b1);
            }
        }
#pragma unroll
        for (int nt = 0; nt < 8; ++nt)
#pragma unroll
            for (int r = 0; r < 4; r++) s[nt][r] *= SCALE2;

        if (kt == qb) {  // causal mask, diagonal tile only
            const int lr = wid * 16 + (lane >> 2);
#pragma unroll
            for (int nt = 0; nt < 8; ++nt) {
                const int lc = nt * 8 + (lane & 3) * 2;
                if (lc     > lr)     s[nt][0] = -1e30f;
                if (lc + 1 > lr)     s[nt][1] = -1e30f;
                if (lc     > lr + 8) s[nt][2] = -1e30f;
                if (lc + 1 > lr + 8) s[nt][3] = -1e30f;
            }
        }

        // ---- online softmax (log2 domain) ----
        float tl = -1e30f, th = -1e30f;
#pragma unroll
        for (int nt = 0; nt < 8; ++nt) {
            tl = fmaxf(tl, fmaxf(s[nt][0], s[nt][1]));
            th = fmaxf(th, fmaxf(s[nt][2], s[nt][3]));
        }
        tl = fmaxf(tl, __shfl_xor_sync(~0u, tl, 1)); tl = fmaxf(tl, __shfl_xor_sync(~0u, tl, 2));
        th = fmaxf(th, __shfl_xor_sync(~0u, th, 1)); th = fmaxf(th, __shfl_xor_sync(~0u, th, 2));

        const float mn_lo = fmaxf(m_lo, tl), mn_hi = fmaxf(m_hi, th);
        const float cor_lo = ex2(m_lo - mn_lo), cor_hi = ex2(m_hi - mn_hi);
        m_lo = mn_lo; m_hi = mn_hi;
        l_lo *= cor_lo; l_hi *= cor_hi;
#pragma unroll
        for (int nt = 0; nt < 8; ++nt) {
            o[nt][0] *= cor_lo; o[nt][1] *= cor_lo;
            o[nt][2] *= cor_hi; o[nt][3] *= cor_hi;
        }

        uint32_t pa[4][4];
#pragma unroll
        for (int nt = 0; nt < 8; ++nt) {
            const float p0 = ex2(s[nt][0] - m_lo), p1 = ex2(s[nt][1] - m_lo);
            const float p2 = ex2(s[nt][2] - m_hi), p3 = ex2(s[nt][3] - m_hi);
            l_lo += p0 + p1; l_hi += p2 + p3;
            const int j = nt >> 1;
            if ((nt & 1) == 0) { pa[j][0] = pack_h2(p0, p1); pa[j][1] = pack_h2(p2, p3); }
            else               { pa[j][2] = pack_h2(p0, p1); pa[j][3] = pack_h2(p2, p3); }
        }

        // ---- O += P @ V (fp16) ----
#pragma unroll
        for (int j = 0; j < 4; ++j) {
            uint32_t vb[4][4];
#pragma unroll
            for (int dp = 0; dp < 4; ++dp) {
                int rr = j * 16 + ((lane >> 3) & 1) * 8 + (lane & 7);
                int cc = dp * 2 + (lane >> 4);
                ldsm4t(vb[dp], SWA(sVu[st], rr, cc));
            }
#pragma unroll
            for (int dp = 0; dp < 4; ++dp) {
                uint32_t b0[2] = { vb[dp][0], vb[dp][1] };
                uint32_t b1[2] = { vb[dp][2], vb[dp][3] };
                mma_f16(o[2 * dp],     pa[j], b0);
                mma_f16(o[2 * dp + 1], pa[j], b1);
            }
        }
        __syncthreads();
    }

    l_lo += __shfl_xor_sync(~0u, l_lo, 1); l_lo += __shfl_xor_sync(~0u, l_lo, 2);
    l_hi += __shfl_xor_sync(~0u, l_hi, 1); l_hi += __shfl_xor_sync(~0u, l_hi, 2);
    const float inv_lo = 1.f / l_lo, inv_hi = 1.f / l_hi;

    // write C pre-rounded to tf32 so out_gemm consumes raw bits
    const int r_lo = q0 + wid * 16 + (lane >> 2);
#pragma unroll
    for (int nt = 0; nt < 8; ++nt) {
        const int col = nt * 8 + (lane & 3) * 2;
        const size_t base = headoff + (size_t)r_lo * DM + col;
        *(float2*)(O + base) = make_float2(
            __uint_as_float(f2tf(o[nt][0] * inv_lo)),
            __uint_as_float(f2tf(o[nt][1] * inv_lo)));
        *(float2*)(O + base + 8 * DM) = make_float2(
            __uint_as_float(f2tf(o[nt][2] * inv_hi)),
            __uint_as_float(f2tf(o[nt][3] * inv_hi)));
    }
#undef SWA
}

// ---------------------------------------------------------------------------
extern "C" void kernel_launch(void* const* d_in, const int* in_sizes, int n_in,
                              void* d_out, int out_size)
{
    const float* X  = (const float*)d_in[0];
    const float* Wq = (const float*)d_in[1];
    const float* bq = (const float*)d_in[2];
    const float* Wk = (const float*)d_in[3];
    const float* bk = (const float*)d_in[4];
    const float* Wv = (const float*)d_in[5];
    const float* bv = (const float*)d_in[6];
    const float* Wo = (const float*)d_in[7];
    const float* bo = (const float*)d_in[8];
    float* out = (float*)d_out;

    float *Xr, *Wr, *Cp; __half *Qh, *Kh, *Vh;
    cudaGetSymbolAddress((void**)&Xr, g_Xr);
    cudaGetSymbolAddress((void**)&Wr, g_Wr);
    cudaGetSymbolAddress((void**)&Qh, g_Qh);
    cudaGetSymbolAddress((void**)&Kh, g_Kh);
    cudaGetSymbolAddress((void**)&Vh, g_Vh);
    cudaGetSymbolAddress((void**)&Cp, g_C);

    cudaFuncSetAttribute(qkv_gemm, cudaFuncAttributeMaxDynamicSharedMemorySize, GEMM_SMEM_BYTES);
    cudaFuncSetAttribute(out_gemm, cudaFuncAttributeMaxDynamicSharedMemorySize, GEMM_SMEM_BYTES);

    const int total4 = NX4 + 4 * NW4;
    round_all<<<total4 / 256, 256>>>(X, Wq, Wk, Wv, Wo, Xr, Wr);

    dim3 gq(DM / 128, MROWS / 128, 3);   // (8, 32, 3)
    qkv_gemm<<<gq, 256, GEMM_SMEM_BYTES>>>(Xr, Wr, bq, bk, bv, Qh, Kh, Vh);

    dim3 ag(LL / 64, NH, BB);            // (32, 16, 2)
    attn_kernel<<<ag, 128>>>(Qh, Kh, Vh, Cp);

    dim3 gg(DM / 128, MROWS / 128);      // (8, 32)
    out_gemm<<<gg, 256, GEMM_SMEM_BYTES>>>(Cp, Wr + 3 * (size_t)DM * DM, bo, out);
}

// round 7
// speedup vs baseline: 6.4832x; 1.0072x over previous
#include <cuda_runtime.h>
#include <cuda_bf16.h>
#include <cuda_fp16.h>
#include <stdint.h>

// B=2, L=2048, H=16, Dh=64, D=1024
#define BB 2
#define LL 2048
#define NH 16
#define DH 64
#define DM 1024
#define MROWS (BB * LL)
#define PAD_TILES 28                   // keys >= 1792 masked; 1792/64
#define SCALE2 0.18033688011112042f    // (1/8) * log2(e)

// Scratch (__device__ globals)
__device__ float  g_Xr[(size_t)MROWS * DM];      // tf32-rounded X
__device__ float  g_Wr[(size_t)4 * DM * DM];     // tf32-rounded Wq|Wk|Wv|Wo
__device__ __half g_Qh[(size_t)MROWS * DM];
__device__ __half g_Kh[(size_t)MROWS * DM];
__device__ __half g_Vh[(size_t)MROWS * DM];
__device__ float  g_C[(size_t)MROWS * DM];       // attn out, tf32-rounded

// ---------------- PTX helpers ----------------
__device__ __forceinline__ uint32_t smem_u32(const void* p) {
    return (uint32_t)__cvta_generic_to_shared(p);
}
__device__ __forceinline__ void cp16(uint32_t s, const void* g) {
    asm volatile("cp.async.cg.shared.global [%0], [%1], 16;" :: "r"(s), "l"(g));
}
__device__ __forceinline__ void cp_commit() {
    asm volatile("cp.async.commit_group;" ::: "memory");
}
template <int N> __device__ __forceinline__ void cp_wait() {
    asm volatile("cp.async.wait_group %0;" :: "n"(N) : "memory");
}
__device__ __forceinline__ uint32_t f2tf(float x) {
    uint32_t u; asm("cvt.rna.tf32.f32 %0, %1;" : "=r"(u) : "f"(x)); return u;
}
__device__ __forceinline__ float ex2(float x) {
    float r; asm("ex2.approx.f32 %0, %1;" : "=f"(r) : "f"(x)); return r;
}
__device__ __forceinline__ void mma_tf32(float* d, const uint32_t* a, const uint32_t* b) {
    asm volatile("mma.sync.aligned.m16n8k8.row.col.f32.tf32.tf32.f32 "
        "{%0,%1,%2,%3},{%4,%5,%6,%7},{%8,%9},{%0,%1,%2,%3};"
        : "+f"(d[0]), "+f"(d[1]), "+f"(d[2]), "+f"(d[3])
        : "r"(a[0]), "r"(a[1]), "r"(a[2]), "r"(a[3]), "r"(b[0]), "r"(b[1]));
}
__device__ __forceinline__ void mma_f16(float* d, const uint32_t* a, const uint32_t* b) {
    asm volatile("mma.sync.aligned.m16n8k16.row.col.f32.f16.f16.f32 "
        "{%0,%1,%2,%3},{%4,%5,%6,%7},{%8,%9},{%0,%1,%2,%3};"
        : "+f"(d[0]), "+f"(d[1]), "+f"(d[2]), "+f"(d[3])
        : "r"(a[0]), "r"(a[1]), "r"(a[2]), "r"(a[3]), "r"(b[0]), "r"(b[1]));
}
__device__ __forceinline__ void ldsm4(uint32_t* r, uint32_t a) {
    asm volatile("ldmatrix.sync.aligned.m8n8.x4.shared.b16 {%0,%1,%2,%3},[%4];"
                 : "=r"(r[0]), "=r"(r[1]), "=r"(r[2]), "=r"(r[3]) : "r"(a));
}
__device__ __forceinline__ void ldsm4t(uint32_t* r, uint32_t a) {
    asm volatile("ldmatrix.sync.aligned.m8n8.x4.trans.shared.b16 {%0,%1,%2,%3},[%4];"
                 : "=r"(r[0]), "=r"(r[1]), "=r"(r[2]), "=r"(r[3]) : "r"(a));
}
__device__ __forceinline__ uint32_t pack_h2(float a, float b) {
    __half2 h = __floats2half2_rn(a, b);
    return *(uint32_t*)&h;
}

// ---------------------------------------------------------------------------
// Prep (single launch): tf32-round X and all 4 weights.
// ---------------------------------------------------------------------------
#define NX4 (MROWS * DM / 4)
#define NW4 (DM * DM / 4)

__global__ __launch_bounds__(256) void round_all(
    const float* __restrict__ X,
    const float* __restrict__ Wq, const float* __restrict__ Wk,
    const float* __restrict__ Wv, const float* __restrict__ Wo,
    float* __restrict__ Xr, float* __restrict__ Wr)
{
    int i = blockIdx.x * 256 + threadIdx.x;
    const float4* src; float4* dst; int j;
    if (i < NX4) {
        src = (const float4*)X; dst = (float4*)Xr; j = i;
    } else {
        int t = i - NX4;
        int w = t / NW4; j = t - w * NW4;
        src = (const float4*)(w == 0 ? Wq : w == 1 ? Wk : w == 2 ? Wv : Wo);
        dst = (float4*)(Wr + (size_t)w * DM * DM);
    }
    float4 v = src[j];
    v.x = __uint_as_float(f2tf(v.x));
    v.y = __uint_as_float(f2tf(v.y));
    v.z = __uint_as_float(f2tf(v.z));
    v.w = __uint_as_float(f2tf(v.w));
    dst[j] = v;
}

// ---------------------------------------------------------------------------
// tf32 GEMM core: pre-rounded inputs, ldmatrix fragment loads, 128x128 tile,
// BK=32, 256 thr, warp 64x32. 3-stage cp.async pipeline, 1 barrier per iter.
// ---------------------------------------------------------------------------
#define GBK 32
#define GLD 36
#define GSTG 3
#define GEMM_SMEM_BYTES (GSTG * 2 * 128 * GLD * 4)   // 110592

#define GEMM_MAIN(APTR, WPTR)                                                   \
    float* As = dsm;                                                            \
    float* Bs = dsm + GSTG * 128 * GLD;                                         \
    const int lane = tid & 31, wid = tid >> 5;                                  \
    const int wm = wid >> 2, wn = wid & 3;                                      \
    /* ldmatrix lane->offset maps */                                            \
    const int a_r = ((lane >> 3) & 1) * 8 + (lane & 7);                         \
    const int a_c = (lane >> 4) * 4;                                            \
    const int b_r = ((lane >> 4) & 1) * 8 + (lane & 7);                         \
    const int b_c = ((lane >> 3) & 1) * 4;                                      \
    float acc[4][4][4];                                                         \
    _Pragma("unroll") for (int i = 0; i < 4; i++)                               \
    _Pragma("unroll") for (int j = 0; j < 4; j++)                               \
    _Pragma("unroll") for (int r = 0; r < 4; r++) acc[i][j][r] = 0.f;           \
    auto load_tiles = [&](int kt, int st) {                                     \
        const int k0 = kt * GBK;                                                \
        float* as = As + st * 128 * GLD;                                        \
        float* bs = Bs + st * 128 * GLD;                                        \
        _Pragma("unroll") for (int j = 0; j < 4; j++) {                         \
            int ci = tid + j * 256;                                             \
            int r = ci >> 3, c = ci & 7;                                        \
            cp16(smem_u32(as + r * GLD + c * 4), (APTR) + (size_t)(row0 + r) * DM + k0 + c * 4); \
            cp16(smem_u32(bs + r * GLD + c * 4), (WPTR) + (size_t)(col0 + r) * DM + k0 + c * 4); \
        }                                                                       \
    };                                                                          \
    load_tiles(0, 0); cp_commit();                                              \
    load_tiles(1, 1); cp_commit();                                              \
    const int NTk = DM / GBK;                                                   \
    int stage = 0;                                                              \
    for (int kt = 0; kt < NTk; ++kt) {                                          \
        if (kt + 1 < NTk) cp_wait<1>(); else cp_wait<0>();                      \
        __syncthreads();                                                        \
        if (kt + 2 < NTk) {                                                     \
            int ns = stage + 2; if (ns >= GSTG) ns -= GSTG;                     \
            load_tiles(kt + 2, ns); cp_commit();                                \
        }                                                                       \
        const uint32_t asu = smem_u32(As + stage * 128 * GLD);                  \
        const uint32_t bsu = smem_u32(Bs + stage * 128 * GLD);                  \
        _Pragma("unroll") for (int ks = 0; ks < 4; ++ks) {                      \
            uint32_t af[4][4], bp[2][4];                                        \
            _Pragma("unroll") for (int mt = 0; mt < 4; ++mt)                    \
                ldsm4(af[mt], asu + 4u * ((wm * 64 + mt * 16 + a_r) * GLD + ks * 8 + a_c)); \
            _Pragma("unroll") for (int np = 0; np < 2; ++np)                    \
                ldsm4(bp[np], bsu + 4u * ((wn * 32 + np * 16 + b_r) * GLD + ks * 8 + b_c)); \
            _Pragma("unroll") for (int mt = 0; mt < 4; ++mt)                    \
            _Pragma("unroll") for (int nt = 0; nt < 4; ++nt)                    \
                mma_tf32(acc[mt][nt], af[mt], &bp[nt >> 1][(nt & 1) * 2]);      \
        }                                                                       \
        if (++stage >= GSTG) stage = 0;                                         \
    }                                                                           \
    __syncthreads();

// QKV fused projection: blockIdx.z selects {Q,K,V}; outputs fp16.
__global__ __launch_bounds__(256) void qkv_gemm(
    const float* __restrict__ X, const float* __restrict__ Wall,
    const float* __restrict__ bq, const float* __restrict__ bk,
    const float* __restrict__ bv,
    __half* __restrict__ Qh, __half* __restrict__ Kh, __half* __restrict__ Vh)
{
    extern __shared__ float dsm[];
    const int tid = threadIdx.x;
    const int row0 = blockIdx.y * 128, col0 = blockIdx.x * 128;
    const int z = blockIdx.z;
    const float* W    = Wall + (size_t)z * DM * DM;
    const float* bias = (z == 0) ? bq : (z == 1) ? bk : bv;
    __half* out       = (z == 0) ? Qh : (z == 1) ? Kh : Vh;

    GEMM_MAIN(X, W)

#pragma unroll
    for (int mt = 0; mt < 4; ++mt) {
        const int r = row0 + wm * 64 + mt * 16 + (lane >> 2);
#pragma unroll
        for (int nt = 0; nt < 4; ++nt) {
            const int c = col0 + wn * 32 + nt * 8 + (lane & 3) * 2;
            const float b0 = bias[c], b1 = bias[c + 1];
            *(uint32_t*)(out + (size_t)r * DM + c) =
                pack_h2(acc[mt][nt][0] + b0, acc[mt][nt][1] + b1);
            *(uint32_t*)(out + (size_t)(r + 8) * DM + c) =
                pack_h2(acc[mt][nt][2] + b0, acc[mt][nt][3] + b1);
        }
    }
}

// Output projection: fp32 out + bias.
__global__ __launch_bounds__(256) void out_gemm(
    const float* __restrict__ A, const float* __restrict__ W,
    const float* __restrict__ bias, float* __restrict__ Y)
{
    extern __shared__ float dsm[];
    const int tid = threadIdx.x;
    const int row0 = blockIdx.y * 128, col0 = blockIdx.x * 128;

    GEMM_MAIN(A, W)

#pragma unroll
    for (int mt = 0; mt < 4; ++mt) {
        const int r = row0 + wm * 64 + mt * 16 + (lane >> 2);
#pragma unroll
        for (int nt = 0; nt < 4; ++nt) {
            const int c = col0 + wn * 32 + nt * 8 + (lane & 3) * 2;
            const float b0 = bias[c], b1 = bias[c + 1];
            *(float2*)(Y + (size_t)r * DM + c) =
                make_float2(acc[mt][nt][0] + b0, acc[mt][nt][1] + b1);
            *(float2*)(Y + (size_t)(r + 8) * DM + c) =
                make_float2(acc[mt][nt][2] + b0, acc[mt][nt][3] + b1);
        }
    }
}

// ---------------------------------------------------------------------------
// Flash attention, fp16 operands, fp32 accum. Br=128 (8 warps), Bc=64.
// ---------------------------------------------------------------------------
__global__ __launch_bounds__(256) void attn_kernel(
    const __half* __restrict__ Q, const __half* __restrict__ K,
    const __half* __restrict__ V, float* __restrict__ O)
{
    __shared__ __align__(1024) __half sQ[128 * 64];
    __shared__ __align__(1024) __half sK[2][64 * 64];
    __shared__ __align__(1024) __half sV[2][64 * 64];

    const int tid = threadIdx.x, lane = tid & 31, wid = tid >> 5;
    const int qb = (int)gridDim.x - 1 - (int)blockIdx.x;     // long blocks first
    const int h = blockIdx.y, b = blockIdx.z;
    const int q0 = qb * 128;
    const size_t headoff = (size_t)b * LL * DM + (size_t)h * DH;

    const uint32_t sQu = smem_u32(sQ);
    const uint32_t sKu[2] = { smem_u32(sK[0]), smem_u32(sK[1]) };
    const uint32_t sVu[2] = { smem_u32(sV[0]), smem_u32(sV[1]) };
#define SWA(base, r, c) ((base) + (uint32_t)(r) * 128u + (uint32_t)(((c) ^ ((r) & 7)) << 4))

    // Q tile: 128 rows x 8 chunks(16B) = 1024 chunks
#pragma unroll
    for (int j = 0; j < 4; ++j) {
        int ci = tid + j * 256;
        int r = ci >> 3, c = ci & 7;
        cp16(SWA(sQu, r, c), Q + headoff + (size_t)(q0 + r) * DM + c * 8);
    }
    auto loadKV = [&](int kt, int st) {
        const int kv0 = kt * 64;
#pragma unroll
        for (int j = 0; j < 2; ++j) {
            int ci = tid + j * 256;
            int r = ci >> 3, c = ci & 7;
            const size_t go = headoff + (size_t)(kv0 + r) * DM + c * 8;
            cp16(SWA(sKu[st], r, c), K + go);
            cp16(SWA(sVu[st], r, c), V + go);
        }
    };
    loadKV(0, 0);
    cp_commit();

    const int NT = min(2 * qb + 2, PAD_TILES);

    float o[8][4];
#pragma unroll
    for (int i = 0; i < 8; i++)
#pragma unroll
        for (int r = 0; r < 4; r++) o[i][r] = 0.f;
    float m_lo = -1e30f, m_hi = -1e30f, l_lo = 0.f, l_hi = 0.f;
    uint32_t qa[4][4];

    for (int kt = 0; kt < NT; ++kt) {
        const int st = kt & 1;
        if (kt + 1 < NT) { loadKV(kt + 1, st ^ 1); cp_commit(); cp_wait<1>(); }
        else             { cp_wait<0>(); }
        __syncthreads();

        if (kt == 0) {
#pragma unroll
            for (int ks = 0; ks < 4; ++ks) {
                int rr = wid * 16 + ((lane >> 3) & 1) * 8 + (lane & 7);
                int cc = ks * 2 + (lane >> 4);
                ldsm4(qa[ks], SWA(sQu, rr, cc));
            }
        }

        // ---- S = Q @ K^T (fp16) ----
        float s[8][4];
#pragma unroll
        for (int i = 0; i < 8; i++)
#pragma unroll
            for (int r = 0; r < 4; r++) s[i][r] = 0.f;
#pragma unroll
        for (int ks = 0; ks < 4; ++ks) {
#pragma unroll
            for (int p2 = 0; p2 < 4; ++p2) {
                uint32_t kb[4];
                int rr = p2 * 16 + ((lane >> 3) & 1) * 8 + (lane & 7);
                int cc = ks * 2 + (lane >> 4);
                ldsm4(kb, SWA(sKu[st], rr, cc));
                uint32_t b0[2] = { kb[0], kb[2] };
                uint32_t b1[2] = { kb[1], kb[3] };
                mma_f16(s[2 * p2],     qa[ks], b0);
                mma_f16(s[2 * p2 + 1], qa[ks], b1);
            }
        }
#pragma unroll
        for (int nt = 0; nt < 8; ++nt)
#pragma unroll
            for (int r = 0; r < 4; r++) s[nt][r] *= SCALE2;

        // causal mask: only the two diagonal tiles (kt >= 2*qb)
        if (kt >= 2 * qb) {
            const int base = (kt - 2 * qb) * 64;      // col offset rel. to q0
            const int lr = wid * 16 + (lane >> 2);    // local q row
#pragma unroll
            for (int nt = 0; nt < 8; ++nt) {
                const int lc = base + nt * 8 + (lane & 3) * 2;
                if (lc     > lr)     s[nt][0] = -1e30f;
                if (lc + 1 > lr)     s[nt][1] = -1e30f;
                if (lc     > lr + 8) s[nt][2] = -1e30f;
                if (lc + 1 > lr + 8) s[nt][3] = -1e30f;
            }
        }

        // ---- online softmax (log2 domain) ----
        float tl = -1e30f, th = -1e30f;
#pragma unroll
        for (int nt = 0; nt < 8; ++nt) {
            tl = fmaxf(tl, fmaxf(s[nt][0], s[nt][1]));
            th = fmaxf(th, fmaxf(s[nt][2], s[nt][3]));
        }
        tl = fmaxf(tl, __shfl_xor_sync(~0u, tl, 1)); tl = fmaxf(tl, __shfl_xor_sync(~0u, tl, 2));
        th = fmaxf(th, __shfl_xor_sync(~0u, th, 1)); th = fmaxf(th, __shfl_xor_sync(~0u, th, 2));

        const float mn_lo = fmaxf(m_lo, tl), mn_hi = fmaxf(m_hi, th);
        const float cor_lo = ex2(m_lo - mn_lo), cor_hi = ex2(m_hi - mn_hi);
        m_lo = mn_lo; m_hi = mn_hi;
        l_lo *= cor_lo; l_hi *= cor_hi;
#pragma unroll
        for (int nt = 0; nt < 8; ++nt) {
            o[nt][0] *= cor_lo; o[nt][1] *= cor_lo;
            o[nt][2] *= cor_hi; o[nt][3] *= cor_hi;
        }

        uint32_t pa[4][4];
#pragma unroll
        for (int nt = 0; nt < 8; ++nt) {
            const float p0 = ex2(s[nt][0] - m_lo), p1 = ex2(s[nt][1] - m_lo);
            const float p2 = ex2(s[nt][2] - m_hi), p3 = ex2(s[nt][3] - m_hi);
            l_lo += p0 + p1; l_hi += p2 + p3;
            const int j = nt >> 1;
            if ((nt & 1) == 0) { pa[j][0] = pack_h2(p0, p1); pa[j][1] = pack_h2(p2, p3); }
            else               { pa[j][2] = pack_h2(p0, p1); pa[j][3] = pack_h2(p2, p3); }
        }

        // ---- O += P @ V (fp16) ----
#pragma unroll
        for (int j = 0; j < 4; ++j) {
            uint32_t vb[4][4];
#pragma unroll
            for (int dp = 0; dp < 4; ++dp) {
                int rr = j * 16 + ((lane >> 3) & 1) * 8 + (lane & 7);
                int cc = dp * 2 + (lane >> 4);
                ldsm4t(vb[dp], SWA(sVu[st], rr, cc));
            }
#pragma unroll
            for (int dp = 0; dp < 4; ++dp) {
                uint32_t b0[2] = { vb[dp][0], vb[dp][1] };
                uint32_t b1[2] = { vb[dp][2], vb[dp][3] };
                mma_f16(o[2 * dp],     pa[j], b0);
                mma_f16(o[2 * dp + 1], pa[j], b1);
            }
        }
        __syncthreads();
    }

    l_lo += __shfl_xor_sync(~0u, l_lo, 1); l_lo += __shfl_xor_sync(~0u, l_lo, 2);
    l_hi += __shfl_xor_sync(~0u, l_hi, 1); l_hi += __shfl_xor_sync(~0u, l_hi, 2);
    const float inv_lo = 1.f / l_lo, inv_hi = 1.f / l_hi;

    // write C pre-rounded to tf32 so out_gemm consumes raw bits
    const int r_lo = q0 + wid * 16 + (lane >> 2);
#pragma unroll
    for (int nt = 0; nt < 8; ++nt) {
        const int col = nt * 8 + (lane & 3) * 2;
        const size_t base = headoff + (size_t)r_lo * DM + col;
        *(float2*)(O + base) = make_float2(
            __uint_as_float(f2tf(o[nt][0] * inv_lo)),
            __uint_as_float(f2tf(o[nt][1] * inv_lo)));
        *(float2*)(O + base + 8 * DM) = make_float2(
            __uint_as_float(f2tf(o[nt][2] * inv_hi)),
            __uint_as_float(f2tf(o[nt][3] * inv_hi)));
    }
#undef SWA
}

// ---------------------------------------------------------------------------
extern "C" void kernel_launch(void* const* d_in, const int* in_sizes, int n_in,
                              void* d_out, int out_size)
{
    const float* X  = (const float*)d_in[0];
    const float* Wq = (const float*)d_in[1];
    const float* bq = (const float*)d_in[2];
    const float* Wk = (const float*)d_in[3];
    const float* bk = (const float*)d_in[4];
    const float* Wv = (const float*)d_in[5];
    const float* bv = (const float*)d_in[6];
    const float* Wo = (const float*)d_in[7];
    const float* bo = (const float*)d_in[8];
    float* out = (float*)d_out;

    float *Xr, *Wr, *Cp; __half *Qh, *Kh, *Vh;
    cudaGetSymbolAddress((void**)&Xr, g_Xr);
    cudaGetSymbolAddress((void**)&Wr, g_Wr);
    cudaGetSymbolAddress((void**)&Qh, g_Qh);
    cudaGetSymbolAddress((void**)&Kh, g_Kh);
    cudaGetSymbolAddress((void**)&Vh, g_Vh);
    cudaGetSymbolAddress((void**)&Cp, g_C);

    cudaFuncSetAttribute(qkv_gemm, cudaFuncAttributeMaxDynamicSharedMemorySize, GEMM_SMEM_BYTES);
    cudaFuncSetAttribute(out_gemm, cudaFuncAttributeMaxDynamicSharedMemorySize, GEMM_SMEM_BYTES);

    const int total4 = NX4 + 4 * NW4;
    round_all<<<total4 / 256, 256>>>(X, Wq, Wk, Wv, Wo, Xr, Wr);

    dim3 gq(DM / 128, MROWS / 128, 3);   // (8, 32, 3)
    qkv_gemm<<<gq, 256, GEMM_SMEM_BYTES>>>(Xr, Wr, bq, bk, bv, Qh, Kh, Vh);

    dim3 ag(LL / 128, NH, BB);           // (16, 16, 2)
    attn_kernel<<<ag, 256>>>(Qh, Kh, Vh, Cp);

    dim3 gg(DM / 128, MROWS / 128);      // (8, 32)
    out_gemm<<<gg, 256, GEMM_SMEM_BYTES>>>(Cp, Wr + 3 * (size_t)DM * DM, bo, out);
}

// round 8
// speedup vs baseline: 8.0569x; 1.2427x over previous
#include <cuda_runtime.h>
#include <cuda_bf16.h>
#include <cuda_fp16.h>
#include <stdint.h>

// B=2, L=2048, H=16, Dh=64, D=1024
#define BB 2
#define LL 2048
#define NH 16
#define DH 64
#define DM 1024
#define MROWS (BB * LL)
#define PAD_TILES 28                   // keys >= 1792 masked; 1792/64
#define SCALE2 0.18033688011112042f    // (1/8) * log2(e)

// Scratch (__device__ globals)
__device__ __half g_Xh[(size_t)MROWS * DM];      // fp16 X
__device__ __half g_Wh[(size_t)4 * DM * DM];     // fp16 Wq|Wk|Wv|Wo
__device__ __half g_Qh[(size_t)MROWS * DM];
__device__ __half g_Kh[(size_t)MROWS * DM];
__device__ __half g_Vh[(size_t)MROWS * DM];
__device__ __half g_Ch[(size_t)MROWS * DM];      // attn out (fp16)

// ---------------- PTX helpers ----------------
__device__ __forceinline__ uint32_t smem_u32(const void* p) {
    return (uint32_t)__cvta_generic_to_shared(p);
}
__device__ __forceinline__ void cp16(uint32_t s, const void* g) {
    asm volatile("cp.async.cg.shared.global [%0], [%1], 16;" :: "r"(s), "l"(g));
}
__device__ __forceinline__ void cp_commit() {
    asm volatile("cp.async.commit_group;" ::: "memory");
}
template <int N> __device__ __forceinline__ void cp_wait() {
    asm volatile("cp.async.wait_group %0;" :: "n"(N) : "memory");
}
__device__ __forceinline__ float ex2(float x) {
    float r; asm("ex2.approx.f32 %0, %1;" : "=f"(r) : "f"(x)); return r;
}
__device__ __forceinline__ void mma_f16(float* d, const uint32_t* a, const uint32_t* b) {
    asm volatile("mma.sync.aligned.m16n8k16.row.col.f32.f16.f16.f32 "
        "{%0,%1,%2,%3},{%4,%5,%6,%7},{%8,%9},{%0,%1,%2,%3};"
        : "+f"(d[0]), "+f"(d[1]), "+f"(d[2]), "+f"(d[3])
        : "r"(a[0]), "r"(a[1]), "r"(a[2]), "r"(a[3]), "r"(b[0]), "r"(b[1]));
}
__device__ __forceinline__ void ldsm4(uint32_t* r, uint32_t a) {
    asm volatile("ldmatrix.sync.aligned.m8n8.x4.shared.b16 {%0,%1,%2,%3},[%4];"
                 : "=r"(r[0]), "=r"(r[1]), "=r"(r[2]), "=r"(r[3]) : "r"(a));
}
__device__ __forceinline__ void ldsm4t(uint32_t* r, uint32_t a) {
    asm volatile("ldmatrix.sync.aligned.m8n8.x4.trans.shared.b16 {%0,%1,%2,%3},[%4];"
                 : "=r"(r[0]), "=r"(r[1]), "=r"(r[2]), "=r"(r[3]) : "r"(a));
}
__device__ __forceinline__ uint32_t pack_h2(float a, float b) {
    __half2 h = __floats2half2_rn(a, b);
    return *(uint32_t*)&h;
}

// ---------------------------------------------------------------------------
// Prep (single launch): convert X + 4 weights to fp16.
// ---------------------------------------------------------------------------
#define NX4 (MROWS * DM / 4)
#define NW4 (DM * DM / 4)

__global__ __launch_bounds__(256) void conv_all(
    const float* __restrict__ X,
    const float* __restrict__ Wq, const float* __restrict__ Wk,
    const float* __restrict__ Wv, const float* __restrict__ Wo,
    __half* __restrict__ Xh, __half* __restrict__ Wh)
{
    int i = blockIdx.x * 256 + threadIdx.x;
    const float4* src; __half* dst; int j;
    if (i < NX4) {
        src = (const float4*)X; dst = Xh; j = i;
    } else {
        int t = i - NX4;
        int w = t / NW4; j = t - w * NW4;
        src = (const float4*)(w == 0 ? Wq : w == 1 ? Wk : w == 2 ? Wv : Wo);
        dst = Wh + (size_t)w * DM * DM;
    }
    float4 v = src[j];
    uint2 o;
    o.x = pack_h2(v.x, v.y);
    o.y = pack_h2(v.z, v.w);
    *(uint2*)(dst + (size_t)j * 4) = o;
}

// ---------------------------------------------------------------------------
// fp16 GEMM core: Y[M,N] = A[M,K] @ W[N,K]^T (+bias in epilogue).
// 128x128 tile, BK=32, 256 thr (8 warps 2x4), warp 64x32.
// 3-stage cp.async pipeline, 1 barrier/iter, pad-40-half rows (conflict-free).
// ---------------------------------------------------------------------------
#define GBK 32
#define GLDH 40                          // halves per row (80B stride)
#define GSTG 3
#define GSTAGE_H (128 * GLDH)            // halves per matrix per stage
#define GEMM_SMEM_BYTES (GSTG * 2 * GSTAGE_H * 2)   // 61440

#define GEMM_MAIN(APTR, WPTR)                                                   \
    __half* As = (__half*)dsm;                                                  \
    __half* Bs = As + GSTG * GSTAGE_H;                                          \
    const int lane = tid & 31, wid = tid >> 5;                                  \
    const int wm = wid >> 2, wn = wid & 3;                                      \
    const int f_r = ((lane >> 3) & 1) * 8 + (lane & 7);  /* ldsm row-in-16 */   \
    const int f_c = (lane >> 4) * 8;                     /* ldsm half-col  */   \
    float acc[4][4][4];                                                         \
    _Pragma("unroll") for (int i = 0; i < 4; i++)                               \
    _Pragma("unroll") for (int j = 0; j < 4; j++)                               \
    _Pragma("unroll") for (int r = 0; r < 4; r++) acc[i][j][r] = 0.f;           \
    auto load_tiles = [&](int kt, int st) {                                     \
        const int k0 = kt * GBK;                                                \
        __half* as = As + st * GSTAGE_H;                                        \
        __half* bs = Bs + st * GSTAGE_H;                                        \
        _Pragma("unroll") for (int j = 0; j < 2; j++) {                         \
            int ci = tid + j * 256;          /* 512 chunks: 128 rows x 4 */     \
            int r = ci >> 2, c = ci & 3;                                        \
            cp16(smem_u32(as + r * GLDH + c * 8), (APTR) + (size_t)(row0 + r) * DM + k0 + c * 8); \
            cp16(smem_u32(bs + r * GLDH + c * 8), (WPTR) + (size_t)(col0 + r) * DM + k0 + c * 8); \
        }                                                                       \
    };                                                                          \
    load_tiles(0, 0); cp_commit();                                              \
    load_tiles(1, 1); cp_commit();                                              \
    const int NTk = DM / GBK;                                                   \
    int stage = 0;                                                              \
    for (int kt = 0; kt < NTk; ++kt) {                                          \
        if (kt + 1 < NTk) cp_wait<1>(); else cp_wait<0>();                      \
        __syncthreads();                                                        \
        if (kt + 2 < NTk) {                                                     \
            int ns = stage + 2; if (ns >= GSTG) ns -= GSTG;                     \
            load_tiles(kt + 2, ns); cp_commit();                                \
        }                                                                       \
        const uint32_t asu = smem_u32(As + stage * GSTAGE_H);                   \
        const uint32_t bsu = smem_u32(Bs + stage * GSTAGE_H);                   \
        _Pragma("unroll") for (int ks = 0; ks < 2; ++ks) {   /* k16 steps */    \
            uint32_t af[4][4], bp[2][4];                                        \
            _Pragma("unroll") for (int mt = 0; mt < 4; ++mt)                    \
                ldsm4(af[mt], asu + 2u * ((wm * 64 + mt * 16 + f_r) * GLDH + ks * 16 + f_c)); \
            _Pragma("unroll") for (int np = 0; np < 2; ++np)                    \
                ldsm4(bp[np], bsu + 2u * ((wn * 32 + np * 16 + f_r) * GLDH + ks * 16 + f_c)); \
            _Pragma("unroll") for (int mt = 0; mt < 4; ++mt)                    \
            _Pragma("unroll") for (int nt = 0; nt < 4; ++nt) {                  \
                uint32_t bb[2] = { bp[nt >> 1][(nt & 1)], bp[nt >> 1][(nt & 1) + 2] }; \
                mma_f16(acc[mt][nt], af[mt], bb);                               \
            }                                                                   \
        }                                                                       \
        if (++stage >= GSTG) stage = 0;                                         \
    }                                                                           \
    __syncthreads();

// QKV fused projection: blockIdx.z selects {Q,K,V}; outputs fp16.
__global__ __launch_bounds__(256) void qkv_gemm(
    const __half* __restrict__ X, const __half* __restrict__ Wall,
    const float* __restrict__ bq, const float* __restrict__ bk,
    const float* __restrict__ bv,
    __half* __restrict__ Qh, __half* __restrict__ Kh, __half* __restrict__ Vh)
{
    extern __shared__ float dsm[];
    const int tid = threadIdx.x;
    const int row0 = blockIdx.y * 128, col0 = blockIdx.x * 128;
    const int z = blockIdx.z;
    const __half* W   = Wall + (size_t)z * DM * DM;
    const float* bias = (z == 0) ? bq : (z == 1) ? bk : bv;
    __half* out       = (z == 0) ? Qh : (z == 1) ? Kh : Vh;

    GEMM_MAIN(X, W)

#pragma unroll
    for (int mt = 0; mt < 4; ++mt) {
        const int r = row0 + wm * 64 + mt * 16 + (lane >> 2);
#pragma unroll
        for (int nt = 0; nt < 4; ++nt) {
            const int c = col0 + wn * 32 + nt * 8 + (lane & 3) * 2;
            const float b0 = bias[c], b1 = bias[c + 1];
            *(uint32_t*)(out + (size_t)r * DM + c) =
                pack_h2(acc[mt][nt][0] + b0, acc[mt][nt][1] + b1);
            *(uint32_t*)(out + (size_t)(r + 8) * DM + c) =
                pack_h2(acc[mt][nt][2] + b0, acc[mt][nt][3] + b1);
        }
    }
}

// Output projection: fp32 out + bias.
__global__ __launch_bounds__(256) void out_gemm(
    const __half* __restrict__ A, const __half* __restrict__ W,
    const float* __restrict__ bias, float* __restrict__ Y)
{
    extern __shared__ float dsm[];
    const int tid = threadIdx.x;
    const int row0 = blockIdx.y * 128, col0 = blockIdx.x * 128;

    GEMM_MAIN(A, W)

#pragma unroll
    for (int mt = 0; mt < 4; ++mt) {
        const int r = row0 + wm * 64 + mt * 16 + (lane >> 2);
#pragma unroll
        for (int nt = 0; nt < 4; ++nt) {
            const int c = col0 + wn * 32 + nt * 8 + (lane & 3) * 2;
            const float b0 = bias[c], b1 = bias[c + 1];
            *(float2*)(Y + (size_t)r * DM + c) =
                make_float2(acc[mt][nt][0] + b0, acc[mt][nt][1] + b1);
            *(float2*)(Y + (size_t)(r + 8) * DM + c) =
                make_float2(acc[mt][nt][2] + b0, acc[mt][nt][3] + b1);
        }
    }
}

// ---------------------------------------------------------------------------
// Flash attention, fp16 operands, fp32 accum. Br=128 (8 warps), Bc=64.
// Output C written directly in fp16.
// ---------------------------------------------------------------------------
__global__ __launch_bounds__(256) void attn_kernel(
    const __half* __restrict__ Q, const __half* __restrict__ K,
    const __half* __restrict__ V, __half* __restrict__ O)
{
    __shared__ __align__(1024) __half sQ[128 * 64];
    __shared__ __align__(1024) __half sK[2][64 * 64];
    __shared__ __align__(1024) __half sV[2][64 * 64];

    const int tid = threadIdx.x, lane = tid & 31, wid = tid >> 5;
    const int qb = (int)gridDim.x - 1 - (int)blockIdx.x;     // long blocks first
    const int h = blockIdx.y, b = blockIdx.z;
    const int q0 = qb * 128;
    const size_t headoff = (size_t)b * LL * DM + (size_t)h * DH;

    const uint32_t sQu = smem_u32(sQ);
    const uint32_t sKu[2] = { smem_u32(sK[0]), smem_u32(sK[1]) };
    const uint32_t sVu[2] = { smem_u32(sV[0]), smem_u32(sV[1]) };
#define SWA(base, r, c) ((base) + (uint32_t)(r) * 128u + (uint32_t)(((c) ^ ((r) & 7)) << 4))

#pragma unroll
    for (int j = 0; j < 4; ++j) {
        int ci = tid + j * 256;
        int r = ci >> 3, c = ci & 7;
        cp16(SWA(sQu, r, c), Q + headoff + (size_t)(q0 + r) * DM + c * 8);
    }
    auto loadKV = [&](int kt, int st) {
        const int kv0 = kt * 64;
#pragma unroll
        for (int j = 0; j < 2; ++j) {
            int ci = tid + j * 256;
            int r = ci >> 3, c = ci & 7;
            const size_t go = headoff + (size_t)(kv0 + r) * DM + c * 8;
            cp16(SWA(sKu[st], r, c), K + go);
            cp16(SWA(sVu[st], r, c), V + go);
        }
    };
    loadKV(0, 0);
    cp_commit();

    const int NT = min(2 * qb + 2, PAD_TILES);

    float o[8][4];
#pragma unroll
    for (int i = 0; i < 8; i++)
#pragma unroll
        for (int r = 0; r < 4; r++) o[i][r] = 0.f;
    float m_lo = -1e30f, m_hi = -1e30f, l_lo = 0.f, l_hi = 0.f;
    uint32_t qa[4][4];

    for (int kt = 0; kt < NT; ++kt) {
        const int st = kt & 1;
        if (kt + 1 < NT) { loadKV(kt + 1, st ^ 1); cp_commit(); cp_wait<1>(); }
        else             { cp_wait<0>(); }
        __syncthreads();

        if (kt == 0) {
#pragma unroll
            for (int ks = 0; ks < 4; ++ks) {
                int rr = wid * 16 + ((lane >> 3) & 1) * 8 + (lane & 7);
                int cc = ks * 2 + (lane >> 4);
                ldsm4(qa[ks], SWA(sQu, rr, cc));
            }
        }

        // ---- S = Q @ K^T (fp16) ----
        float s[8][4];
#pragma unroll
        for (int i = 0; i < 8; i++)
#pragma unroll
            for (int r = 0; r < 4; r++) s[i][r] = 0.f;
#pragma unroll
        for (int ks = 0; ks < 4; ++ks) {
#pragma unroll
            for (int p2 = 0; p2 < 4; ++p2) {
                uint32_t kb[4];
                int rr = p2 * 16 + ((lane >> 3) & 1) * 8 + (lane & 7);
                int cc = ks * 2 + (lane >> 4);
                ldsm4(kb, SWA(sKu[st], rr, cc));
                uint32_t b0[2] = { kb[0], kb[2] };
                uint32_t b1[2] = { kb[1], kb[3] };
                mma_f16(s[2 * p2],     qa[ks], b0);
                mma_f16(s[2 * p2 + 1], qa[ks], b1);
            }
        }
#pragma unroll
        for (int nt = 0; nt < 8; ++nt)
#pragma unroll
            for (int r = 0; r < 4; r++) s[nt][r] *= SCALE2;

        // causal mask: only the two diagonal tiles (kt >= 2*qb)
        if (kt >= 2 * qb) {
            const int base = (kt - 2 * qb) * 64;
            const int lr = wid * 16 + (lane >> 2);
#pragma unroll
            for (int nt = 0; nt < 8; ++nt) {
                const int lc = base + nt * 8 + (lane & 3) * 2;
                if (lc     > lr)     s[nt][0] = -1e30f;
                if (lc + 1 > lr)     s[nt][1] = -1e30f;
                if (lc     > lr + 8) s[nt][2] = -1e30f;
                if (lc + 1 > lr + 8) s[nt][3] = -1e30f;
            }
        }

        // ---- online softmax (log2 domain) ----
        float tl = -1e30f, th = -1e30f;
#pragma unroll
        for (int nt = 0; nt < 8; ++nt) {
            tl = fmaxf(tl, fmaxf(s[nt][0], s[nt][1]));
            th = fmaxf(th, fmaxf(s[nt][2], s[nt][3]));
        }
        tl = fmaxf(tl, __shfl_xor_sync(~0u, tl, 1)); tl = fmaxf(tl, __shfl_xor_sync(~0u, tl, 2));
        th = fmaxf(th, __shfl_xor_sync(~0u, th, 1)); th = fmaxf(th, __shfl_xor_sync(~0u, th, 2));

        const float mn_lo = fmaxf(m_lo, tl), mn_hi = fmaxf(m_hi, th);
        const float cor_lo = ex2(m_lo - mn_lo), cor_hi = ex2(m_hi - mn_hi);
        m_lo = mn_lo; m_hi = mn_hi;
        l_lo *= cor_lo; l_hi *= cor_hi;
#pragma unroll
        for (int nt = 0; nt < 8; ++nt) {
            o[nt][0] *= cor_lo; o[nt][1] *= cor_lo;
            o[nt][2] *= cor_hi; o[nt][3] *= cor_hi;
        }

        uint32_t pa[4][4];
#pragma unroll
        for (int nt = 0; nt < 8; ++nt) {
            const float p0 = ex2(s[nt][0] - m_lo), p1 = ex2(s[nt][1] - m_lo);
            const float p2 = ex2(s[nt][2] - m_hi), p3 = ex2(s[nt][3] - m_hi);
            l_lo += p0 + p1; l_hi += p2 + p3;
            const int j = nt >> 1;
            if ((nt & 1) == 0) { pa[j][0] = pack_h2(p0, p1); pa[j][1] = pack_h2(p2, p3); }
            else               { pa[j][2] = pack_h2(p0, p1); pa[j][3] = pack_h2(p2, p3); }
        }

        // ---- O += P @ V (fp16) ----
#pragma unroll
        for (int j = 0; j < 4; ++j) {
            uint32_t vb[4][4];
#pragma unroll
            for (int dp = 0; dp < 4; ++dp) {
                int rr = j * 16 + ((lane >> 3) & 1) * 8 + (lane & 7);
                int cc = dp * 2 + (lane >> 4);
                ldsm4t(vb[dp], SWA(sVu[st], rr, cc));
            }
#pragma unroll
            for (int dp = 0; dp < 4; ++dp) {
                uint32_t b0[2] = { vb[dp][0], vb[dp][1] };
                uint32_t b1[2] = { vb[dp][2], vb[dp][3] };
                mma_f16(o[2 * dp],     pa[j], b0);
                mma_f16(o[2 * dp + 1], pa[j], b1);
            }
        }
        __syncthreads();
    }

    l_lo += __shfl_xor_sync(~0u, l_lo, 1); l_lo += __shfl_xor_sync(~0u, l_lo, 2);
    l_hi += __shfl_xor_sync(~0u, l_hi, 1); l_hi += __shfl_xor_sync(~0u, l_hi, 2);
    const float inv_lo = 1.f / l_lo, inv_hi = 1.f / l_hi;

    const int r_lo = q0 + wid * 16 + (lane >> 2);
#pragma unroll
    for (int nt = 0; nt < 8; ++nt) {
        const int col = nt * 8 + (lane & 3) * 2;
        const size_t base = headoff + (size_t)r_lo * DM + col;
        *(uint32_t*)(O + base)          = pack_h2(o[nt][0] * inv_lo, o[nt][1] * inv_lo);
        *(uint32_t*)(O + base + 8 * DM) = pack_h2(o[nt][2] * inv_hi, o[nt][3] * inv_hi);
    }
#undef SWA
}

// ---------------------------------------------------------------------------
extern "C" void kernel_launch(void* const* d_in, const int* in_sizes, int n_in,
                              void* d_out, int out_size)
{
    const float* X  = (const float*)d_in[0];
    const float* Wq = (const float*)d_in[1];
    const float* bq = (const float*)d_in[2];
    const float* Wk = (const float*)d_in[3];
    const float* bk = (const float*)d_in[4];
    const float* Wv = (const float*)d_in[5];
    const float* bv = (const float*)d_in[6];
    const float* Wo = (const float*)d_in[7];
    const float* bo = (const float*)d_in[8];
    float* out = (float*)d_out;

    __half *Xh, *Wh, *Qh, *Kh, *Vh, *Ch;
    cudaGetSymbolAddress((void**)&Xh, g_Xh);
    cudaGetSymbolAddress((void**)&Wh, g_Wh);
    cudaGetSymbolAddress((void**)&Qh, g_Qh);
    cudaGetSymbolAddress((void**)&Kh, g_Kh);
    cudaGetSymbolAddress((void**)&Vh, g_Vh);
    cudaGetSymbolAddress((void**)&Ch, g_Ch);

    cudaFuncSetAttribute(qkv_gemm, cudaFuncAttributeMaxDynamicSharedMemorySize, GEMM_SMEM_BYTES);
    cudaFuncSetAttribute(out_gemm, cudaFuncAttributeMaxDynamicSharedMemorySize, GEMM_SMEM_BYTES);

    const int total4 = NX4 + 4 * NW4;
    conv_all<<<total4 / 256, 256>>>(X, Wq, Wk, Wv, Wo, Xh, Wh);

    dim3 gq(DM / 128, MROWS / 128, 3);   // (8, 32, 3)
    qkv_gemm<<<gq, 256, GEMM_SMEM_BYTES>>>(Xh, Wh, bq, bk, bv, Qh, Kh, Vh);

    dim3 ag(LL / 128, NH, BB);           // (16, 16, 2)
    attn_kernel<<<ag, 256>>>(Qh, Kh, Vh, Ch);

    dim3 gg(DM / 128, MROWS / 128);      // (8, 32)
    out_gemm<<<gg, 256, GEMM_SMEM_BYTES>>>(Ch, Wh + 3 * (size_t)DM * DM, bo, out);
}